// round 14
// baseline (speedup 1.0000x reference)
#include <cuda_runtime.h>
#include <cuda_bf16.h>
#include <math.h>

#define BN_ 4096      // batch
#define DD  128       // feature dim
#define HH  256       // hidden
#define TT  64        // time emb
#define KNN 10
#define NL  2
#define ZW  448       // Z row width: [s(256) | x(128) | t(64)]

typedef unsigned long long u64;
typedef unsigned int u32;
typedef unsigned short u16;

// ---------------- static scratch ----------------
__device__ __align__(128) float g_z[BN_*ZW];             // [s | x | t] fp32
__device__ __align__(128) u16   g_zh[BN_*ZW], g_zl[BN_*ZW];      // bf16 planes of Z
__device__ __align__(128) float g_dist[(size_t)BN_*BN_]; // 64 MB
__device__ __align__(128) int   g_idx[BN_*KNN];
__device__ __align__(128) float g_ew[BN_*KNN];
__device__ __align__(128) float g_pp[BN_*HH];
__device__ __align__(128) float g_qq[BN_*HH];
__device__ __align__(128) u16   g_cath[BN_*2*HH], g_catl[BN_*2*HH];
__device__ __align__(128) u16   g_u1h[BN_*HH],    g_u1l[BN_*HH];
__device__ __align__(128) float g_wp[NL*384*HH];         // [W1a; W1c] fp32 staging
__device__ __align__(128) float g_wq[NL*448*HH];         // [W1b; -W1c; W1d] fp32 staging
__device__ __align__(128) float g_wcat[NL*2*HH*HH];      // [Wu1a; Wm2@Wu1b] fp32 staging
__device__ __align__(128) float g_b2u[NL*HH];            // bm2@Wu1b + bu1
__device__ __align__(128) float g_bout[DD];              // centered b_out
// pre-split bf16 weight planes
__device__ __align__(128) u16 g_win_h[DD*HH],        g_win_l[DD*HH];
__device__ __align__(128) u16 g_wp_h[NL*384*HH],     g_wp_l[NL*384*HH];
__device__ __align__(128) u16 g_wq_h[NL*448*HH],     g_wq_l[NL*448*HH];
__device__ __align__(128) u16 g_wcat_h[NL*2*HH*HH],  g_wcat_l[NL*2*HH*HH];
__device__ __align__(128) u16 g_wu2_h[NL*HH*HH],     g_wu2_l[NL*HH*HH];
__device__ __align__(128) u16 g_wout_h[HH*DD],       g_wout_l[HH*DD];
__device__ __align__(128) u16 g_wu1b_h[NL*HH*HH],    g_wu1b_l[NL*HH*HH];
__device__ __align__(128) u16 g_wm2_h[NL*HH*HH],     g_wm2_l[NL*HH*HH];

__device__ __forceinline__ float gelu_exact(float x) {
    return 0.5f * x * (1.0f + erff(x * 0.70710678118654752440f));
}

__device__ __forceinline__ u64 pack_f2(float x, float y) {
    u64 r; asm("mov.b64 %0, {%1, %2};" : "=l"(r) : "f"(x), "f"(y)); return r;
}
__device__ __forceinline__ float2 unpack_f2(u64 v) {
    float2 f; asm("mov.b64 {%0, %1}, %2;" : "=f"(f.x), "=f"(f.y) : "l"(v)); return f;
}
__device__ __forceinline__ void l1_acc(u64& acc, u64 a, u64 nb) {
    u64 d;
    asm("add.rn.f32x2 %0, %1, %2;" : "=l"(d) : "l"(a), "l"(nb));
    u32 lo = (u32)d & 0x7fffffffu;
    u32 hi = (u32)(d >> 32) & 0x7fffffffu;
    u64 m = ((u64)hi << 32) | (u64)lo;
    asm("add.rn.f32x2 %0, %0, %1;" : "+l"(acc) : "l"(m));
}

// ---------------- bf16 helpers ----------------
__device__ __forceinline__ void split_pair(float x0, float x1, u32& hi, u32& lo) {
    asm("cvt.rn.bf16x2.f32 %0, %1, %2;" : "=r"(hi) : "f"(x1), "f"(x0));
    float h0 = __uint_as_float(hi << 16);
    float h1 = __uint_as_float(hi & 0xffff0000u);
    float l0 = x0 - h0, l1 = x1 - h1;
    asm("cvt.rn.bf16x2.f32 %0, %1, %2;" : "=r"(lo) : "f"(l1), "f"(l0));
}
__device__ __forceinline__ void mma16(float* c, const u32* a, const u32* b) {
    asm volatile("mma.sync.aligned.m16n8k16.row.col.f32.bf16.bf16.f32 "
                 "{%0,%1,%2,%3}, {%4,%5,%6,%7}, {%8,%9}, {%0,%1,%2,%3};"
                 : "+f"(c[0]), "+f"(c[1]), "+f"(c[2]), "+f"(c[3])
                 : "r"(a[0]), "r"(a[1]), "r"(a[2]), "r"(a[3]),
                   "r"(b[0]), "r"(b[1]));
}
__device__ __forceinline__ void ldsm2t(u32& r0, u32& r1, u32 addr) {
    asm volatile("ldmatrix.sync.aligned.m8n8.x2.trans.shared.b16 {%0,%1}, [%2];"
                 : "=r"(r0), "=r"(r1) : "r"(addr));
}
__device__ __forceinline__ void ldsm4(u32* r, u32 addr) {
    asm volatile("ldmatrix.sync.aligned.m8n8.x4.shared.b16 {%0,%1,%2,%3}, [%4];"
                 : "=r"(r[0]), "=r"(r[1]), "=r"(r[2]), "=r"(r[3]) : "r"(addr));
}
__device__ __forceinline__ u32 smem_u32(const void* p) {
    return (u32)__cvta_generic_to_shared(p);
}
__device__ __forceinline__ void cp16(u32 dst, const void* src) {
    asm volatile("cp.async.cg.shared.global [%0], [%1], 16;\n" :: "r"(dst), "l"(src));
}
__device__ __forceinline__ void split1(float x, u16* hi, u16* lo, size_t i) {
    __nv_bfloat16 h = __float2bfloat16_rn(x);
    float hf = __bfloat162float(h);
    __nv_bfloat16 l = __float2bfloat16_rn(x - hf);
    hi[i] = *(u16*)&h;
    lo[i] = *(u16*)&l;
}

// ---------------- build Z = [s(later) | x | t] + planes ----------------
__global__ void build_z_kernel(const float* __restrict__ xc, const float* __restrict__ d0,
                               const float* __restrict__ d1, const float* __restrict__ d2,
                               const float* __restrict__ xo, const float* __restrict__ te,
                               float* __restrict__ Z, u16* __restrict__ Zh, u16* __restrict__ Zl) {
    int i = blockIdx.x;
    int t = threadIdx.x; // 192
    float v; int c;
    if (t < 128) {
        if (t < 64)       v = xc[i*64 + t];
        else if (t < 80)  v = d0[i*16 + (t-64)];
        else if (t < 96)  v = d1[i*16 + (t-80)];
        else if (t < 112) v = d2[i*16 + (t-96)];
        else              v = xo[i*16 + (t-112)];
        c = 256 + t;
    } else {
        v = te[i*TT + (t-128)];
        c = 384 + (t-128);
    }
    size_t o = (size_t)i*ZW + c;
    Z[o] = v;
    split1(v, Zh, Zl, o);
}

// ---------------- rearranged weights (fp32 staging) ----------------
__global__ void rearrange_w_kernel(const float* __restrict__ Wm1,
                                   const float* __restrict__ Wu1,
                                   float* __restrict__ Wp, float* __restrict__ Wq,
                                   float* __restrict__ Wcat) {
    int idx = blockIdx.x * 256 + threadIdx.x;
    int l = idx / (1088*HH);
    int r2 = idx - l*(1088*HH);
    int r = r2 / HH, c = r2 - (r2/HH)*HH;
    const float* w = Wm1 + (size_t)l*704*HH;
    if (r < 384) {
        int sr = (r < 256) ? r : (512 + (r - 256));
        Wp[(size_t)l*384*HH + r*HH + c] = w[sr*HH + c];
    } else if (r < 832) {
        int rq = r - 384;
        float sgn = 1.0f; int sr;
        if (rq < 256)      sr = 256 + rq;
        else if (rq < 384) { sr = 512 + (rq - 256); sgn = -1.0f; }
        else               sr = 640 + (rq - 384);
        Wq[(size_t)l*448*HH + rq*HH + c] = sgn * w[sr*HH + c];
    } else {
        int rc = r - 832;
        Wcat[(size_t)l*2*HH*HH + rc*HH + c] = Wu1[(size_t)l*2*HH*HH + rc*HH + c];
    }
}

// ---------------- fold bias: b2u = bm2 @ Wu1b + bu1 ----------------
__global__ void bias_u1_kernel(const float* __restrict__ bm2, const float* __restrict__ bu1,
                               const float* __restrict__ Wu1, float* __restrict__ b2u) {
    int l = blockIdx.x;
    int c = threadIdx.x;
    const float* wb = Wu1 + (size_t)l*2*HH*HH + (size_t)HH*HH;
    float acc = bu1[l*HH + c];
    for (int k = 0; k < HH; k++) acc = fmaf(bm2[l*HH + k], wb[k*HH + c], acc);
    b2u[l*HH + c] = acc;
}

// ---------------- centered b_out ----------------
__global__ void bout_kernel(const float* __restrict__ b_out, float* __restrict__ bout_c) {
    int c = threadIdx.x; // 128
    float v = b_out[c];
    if (c >= 64 && c < 112) {
        int blk = 64 + (((c - 64) >> 4) << 4);
        float m = 0.0f;
        #pragma unroll
        for (int q = 0; q < 16; q++) m += b_out[blk + q];
        v -= m * (1.0f/16.0f);
    }
    bout_c[c] = v;
}

// one launch for all independent weight splits (W_out centered on the fly)
#define SP0 (DD*HH)
#define SP1 (SP0 + NL*384*HH)
#define SP2 (SP1 + NL*448*HH)
#define SP3 (SP2 + NL*HH*HH)
#define SP4 (SP3 + HH*DD)
#define SP5 (SP4 + NL*HH*HH)
#define SP6 (SP5 + NL*HH*HH)
__global__ void wsplit_all_kernel(const float* __restrict__ W_in,
                                  const float* __restrict__ wp,
                                  const float* __restrict__ wq,
                                  const float* __restrict__ Wu2,
                                  const float* __restrict__ W_out,
                                  const float* __restrict__ Wu1,
                                  const float* __restrict__ Wm2,
                                  u16* win_h, u16* win_l, u16* wp_h, u16* wp_l,
                                  u16* wq_h, u16* wq_l, u16* wu2_h, u16* wu2_l,
                                  u16* wout_h, u16* wout_l, u16* wu1b_h, u16* wu1b_l,
                                  u16* wm2_h, u16* wm2_l) {
    int i = blockIdx.x * 256 + threadIdx.x;
    if (i < SP0) {
        split1(W_in[i], win_h, win_l, i);
    } else if (i < SP1) {
        int j = i - SP0; split1(wp[j], wp_h, wp_l, j);
    } else if (i < SP2) {
        int j = i - SP1; split1(wq[j], wq_h, wq_l, j);
    } else if (i < SP3) {
        int j = i - SP2; split1(Wu2[j], wu2_h, wu2_l, j);
    } else if (i < SP4) {
        int j = i - SP3;                 // r*DD + c
        int c = j & (DD-1);
        float v = W_out[j];
        if (c >= 64 && c < 112) {        // center categorical blocks (exact linear fold)
            int blk = j - c + 64 + (((c - 64) >> 4) << 4);
            float m = 0.0f;
            #pragma unroll
            for (int q = 0; q < 16; q++) m += W_out[blk + q];
            v -= m * (1.0f/16.0f);
        }
        split1(v, wout_h, wout_l, j);
    } else if (i < SP5) {
        int j = i - SP4;
        int l = j >> 16;
        int e = j & 65535;
        split1(Wu1[(size_t)l*2*HH*HH + (size_t)HH*HH + e], wu1b_h, wu1b_l, j);
    } else if (i < SP6) {
        int j = i - SP5; split1(Wm2[j], wm2_h, wm2_l, j);
    }
}

__global__ void wsplit_kernel(const float* __restrict__ src, u16* __restrict__ hi,
                              u16* __restrict__ lo, int n) {
    int i = blockIdx.x * 256 + threadIdx.x;
    if (i >= n) return;
    split1(src[i], hi, lo, i);
}

// ---------------- symmetric L1 cdist, 128x128 tiles, conflict-free B layout ----------------
// tileBase selects the tile range: tiles enumerated r-ascending; tiles with r<=15
// fully cover dist rows [0,2048) (normal + transposed contributions).
__global__ __launch_bounds__(512) void cdist_kernel(const float* __restrict__ X,
                                                    float* __restrict__ Dist,
                                                    int tileBase) {
    __shared__ u64 As2[16][128];
    __shared__ u64 Bs2[4][17][33];   // [j][kk][col4], padded against store conflicts
    int r = 0, rem = blockIdx.x + tileBase;
    while (rem >= 32 - r) { rem -= 32 - r; r++; }
    int bm = r * 128, bn = (r + rem) * 128;

    int tid = threadIdx.x;
    int ty = tid >> 5;
    int tx = tid & 31;
    u64 acc2[8][4];
    #pragma unroll
    for (int i = 0; i < 8; i++)
        #pragma unroll
        for (int j = 0; j < 4; j++) acc2[i][j] = 0ull;

    int lrow = tid >> 2;
    int lq   = (tid & 3) * 8;
    int jb = lrow & 3, cb = lrow >> 2;
    int ks = lq >> 1;          // (tid&3)*4

    for (int k0 = 0; k0 < DD; k0 += 32) {
        float4 va0 = *(const float4*)&X[(size_t)(bm + lrow)*ZW + k0 + lq];
        float4 va1 = *(const float4*)&X[(size_t)(bm + lrow)*ZW + k0 + lq + 4];
        As2[ks+0][lrow] = pack_f2(va0.x, va0.y);
        As2[ks+1][lrow] = pack_f2(va0.z, va0.w);
        As2[ks+2][lrow] = pack_f2(va1.x, va1.y);
        As2[ks+3][lrow] = pack_f2(va1.z, va1.w);
        float4 vb0 = *(const float4*)&X[(size_t)(bn + lrow)*ZW + k0 + lq];
        float4 vb1 = *(const float4*)&X[(size_t)(bn + lrow)*ZW + k0 + lq + 4];
        Bs2[jb][ks+0][cb] = pack_f2(-vb0.x, -vb0.y);
        Bs2[jb][ks+1][cb] = pack_f2(-vb0.z, -vb0.w);
        Bs2[jb][ks+2][cb] = pack_f2(-vb1.x, -vb1.y);
        Bs2[jb][ks+3][cb] = pack_f2(-vb1.z, -vb1.w);
        __syncthreads();
        #pragma unroll
        for (int kk = 0; kk < 16; kk++) {
            u64 a2[8], b2[4];
            #pragma unroll
            for (int i = 0; i < 8; i++) a2[i] = As2[kk][ty*8 + i];
            #pragma unroll
            for (int j = 0; j < 4; j++) b2[j] = Bs2[j][kk][tx];
            #pragma unroll
            for (int i = 0; i < 8; i++)
                #pragma unroll
                for (int j = 0; j < 4; j++) l1_acc(acc2[i][j], a2[i], b2[j]);
        }
        __syncthreads();
    }
    float res[8][4];
    #pragma unroll
    for (int i = 0; i < 8; i++)
        #pragma unroll
        for (int j = 0; j < 4; j++) {
            float2 f = unpack_f2(acc2[i][j]);
            res[i][j] = f.x + f.y;
        }
    if (bm == bn) {
        #pragma unroll
        for (int i = 0; i < 8; i++)
            #pragma unroll
            for (int j = 0; j < 4; j++)
                if (ty*8 + i == tx*4 + j) res[i][j] = __int_as_float(0x7f800000);
    }
    #pragma unroll
    for (int i = 0; i < 8; i++) {
        float4 v = make_float4(res[i][0], res[i][1], res[i][2], res[i][3]);
        *(float4*)&Dist[(size_t)(bm + ty*8 + i)*BN_ + bn + tx*4] = v;
    }
    if (bm != bn) {
        #pragma unroll
        for (int j = 0; j < 4; j++) {
            float4 v0 = make_float4(res[0][j], res[1][j], res[2][j], res[3][j]);
            float4 v1 = make_float4(res[4][j], res[5][j], res[6][j], res[7][j]);
            size_t o = (size_t)(bn + tx*4 + j)*BN_ + bm + ty*8;
            *(float4*)&Dist[o]     = v0;
            *(float4*)&Dist[o + 4] = v1;
        }
    }
}

// ---------------- top-K: warp per row, 2-pass with provable prefilter ----------------
__global__ __launch_bounds__(256) void topk_kernel(const float* __restrict__ Dist,
                                                   int* __restrict__ Idx,
                                                   float* __restrict__ Ew,
                                                   int rowBase) {
    __shared__ float sdm[8][32*KNN];
    __shared__ int   sim[8][32*KNN];
    int warp = threadIdx.x >> 5;
    int lane = threadIdx.x & 31;
    int i = rowBase + blockIdx.x * 8 + warp;
    const float4* row = (const float4*)(Dist + (size_t)i * BN_);
    const float INF = __int_as_float(0x7f800000);

    float mn = INF;
    #pragma unroll 4
    for (int it = 0; it < 32; it++) {
        float4 d4 = row[it*32 + lane];
        mn = fminf(mn, fminf(fminf(d4.x, d4.y), fminf(d4.z, d4.w)));
    }
    float cur = mn, T = INF;
    #pragma unroll
    for (int q = 0; q < KNN; q++) {
        float wmin = cur;
        #pragma unroll
        for (int off = 16; off >= 1; off >>= 1)
            wmin = fminf(wmin, __shfl_xor_sync(0xffffffffu, wmin, off));
        T = wmin;
        u32 ballot = __ballot_sync(0xffffffffu, cur == wmin);
        int first = __ffs(ballot) - 1;
        if (lane == first) cur = INF;
    }

    float bd[KNN]; int bi[KNN];
    #pragma unroll
    for (int q = 0; q < KNN; q++) { bd[q] = INF; bi[q] = 0x7fffffff; }
    #pragma unroll 4
    for (int it = 0; it < 32; it++) {
        int jv = it*32 + lane;
        float4 d4 = row[jv];
        float dv[4] = {d4.x, d4.y, d4.z, d4.w};
        #pragma unroll
        for (int q4 = 0; q4 < 4; q4++) {
            float d = dv[q4];
            if (d <= T) {
                float dd = d; int ii = jv*4 + q4;
                #pragma unroll
                for (int q = 0; q < KNN; q++) {
                    bool c = dd < bd[q];
                    float tf = bd[q]; int ti = bi[q];
                    bd[q] = c ? dd : bd[q]; bi[q] = c ? ii : bi[q];
                    dd = c ? tf : dd;       ii = c ? ti : ii;
                }
            }
        }
    }

    float* sdw = sdm[warp];
    int*   siw = sim[warp];
    #pragma unroll
    for (int q = 0; q < KNN; q++) { sdw[lane*KNN + q] = bd[q]; siw[lane*KNN + q] = bi[q]; }
    __syncwarp();
    #pragma unroll
    for (int stride = 1; stride < 32; stride <<= 1) {
        if ((lane & (2*stride - 1)) == 0) {
            float* da = sdw + lane*KNN;            int* ia = siw + lane*KNN;
            float* db = sdw + (lane+stride)*KNN;   int* ib = siw + (lane+stride)*KNN;
            float od[KNN]; int oi[KNN];
            int pa = 0, pb = 0;
            #pragma unroll
            for (int q = 0; q < KNN; q++) {
                float va = da[pa], vb = db[pb];
                bool c = va <= vb;
                od[q] = c ? va : vb;
                oi[q] = c ? ia[pa] : ib[pb];
                pa += c; pb += !c;
            }
            #pragma unroll
            for (int q = 0; q < KNN; q++) { da[q] = od[q]; ia[q] = oi[q]; }
        }
        __syncwarp();
    }

    if (lane == 0) {
        float d[KNN]; int ix[KNN];
        #pragma unroll
        for (int q = 0; q < KNN; q++) { d[q] = sdw[q]; ix[q] = siw[q]; }
        float w[KNN], sum = 0.0f;
        float dmin = d[0];
        #pragma unroll
        for (int q = 0; q < KNN; q++) { w[q] = expf(dmin - d[q]); sum += w[q]; }
        float inv = 1.0f / sum;
        #pragma unroll
        for (int q = 0; q < KNN; q++) {
            Ew[i*KNN + q] = w[q] * inv;
            Idx[i*KNN + q] = ix[q];
        }
    }
}

// ---- bf16 tensor-core GEMM: pre-split A AND B planes, pure-ldmatrix mainloop ----
template<int ACT, int ACC>
__device__ __forceinline__ void gemm_bf(const u16* __restrict__ Ahi_g,
                                        const u16* __restrict__ Alo_g, int lda,
                                        const u16* __restrict__ Whi,
                                        const u16* __restrict__ Wlo, int ldw,
                                        const float* __restrict__ bias,
                                        float* __restrict__ C,
                                        u16* __restrict__ Chi, u16* __restrict__ Clo,
                                        int ldc, int K, int bm, int bn) {
    __shared__ alignas(16) u16 Ah[2][64][40];
    __shared__ alignas(16) u16 Al[2][64][40];
    __shared__ alignas(16) u16 Bh[2][32][72];
    __shared__ alignas(16) u16 Bl[2][32][72];
    int tid = threadIdx.x, lane = tid & 31, wid = tid >> 5;
    int wm = (wid >> 1) * 32, wn = (wid & 1) * 32;
    float c[2][4][4];
    #pragma unroll
    for (int mb = 0; mb < 2; mb++)
        #pragma unroll
        for (int nb = 0; nb < 4; nb++)
            #pragma unroll
            for (int q = 0; q < 4; q++) c[mb][nb][q] = 0.0f;

    int as0 = tid, as1 = tid + 128;
    int ar0 = as0 >> 2, ao0 = (as0 & 3) * 8;
    int ar1 = as1 >> 2, ao1 = (as1 & 3) * 8;
    int brow = tid >> 2, bcol = (tid & 3) * 16;

    const u16* ah0 = &Ahi_g[(size_t)(bm + ar0)*lda + ao0];
    const u16* ah1 = &Ahi_g[(size_t)(bm + ar1)*lda + ao1];
    const u16* al0 = &Alo_g[(size_t)(bm + ar0)*lda + ao0];
    const u16* al1 = &Alo_g[(size_t)(bm + ar1)*lda + ao1];
    const u16* bh0 = &Whi[(size_t)brow*ldw + bn + bcol];
    const u16* bl0 = &Wlo[(size_t)brow*ldw + bn + bcol];

    {
        cp16(smem_u32(&Ah[0][ar0][ao0]), ah0);
        cp16(smem_u32(&Ah[0][ar1][ao1]), ah1);
        cp16(smem_u32(&Al[0][ar0][ao0]), al0);
        cp16(smem_u32(&Al[0][ar1][ao1]), al1);
        u32 dh = smem_u32(&Bh[0][brow][bcol]);
        cp16(dh, bh0); cp16(dh+16, bh0+8);
        u32 dl = smem_u32(&Bl[0][brow][bcol]);
        cp16(dl, bl0); cp16(dl+16, bl0+8);
        asm volatile("cp.async.commit_group;\n");
    }

    int nch = K >> 5;
    for (int ch = 0; ch < nch; ch++) {
        int buf = ch & 1;
        if (ch + 1 < nch) {
            int k0 = (ch + 1) * 32;
            cp16(smem_u32(&Ah[buf^1][ar0][ao0]), ah0 + k0);
            cp16(smem_u32(&Ah[buf^1][ar1][ao1]), ah1 + k0);
            cp16(smem_u32(&Al[buf^1][ar0][ao0]), al0 + k0);
            cp16(smem_u32(&Al[buf^1][ar1][ao1]), al1 + k0);
            u32 dh = smem_u32(&Bh[buf^1][brow][bcol]);
            const u16* sh = bh0 + (size_t)k0*ldw;
            cp16(dh, sh); cp16(dh+16, sh+8);
            u32 dl = smem_u32(&Bl[buf^1][brow][bcol]);
            const u16* sl = bl0 + (size_t)k0*ldw;
            cp16(dl, sl); cp16(dl+16, sl+8);
            asm volatile("cp.async.commit_group;\n");
            asm volatile("cp.async.wait_group 1;\n");
        } else {
            asm volatile("cp.async.wait_group 0;\n");
        }
        __syncthreads();
        #pragma unroll
        for (int ks = 0; ks < 32; ks += 16) {
            u32 ahi[2][4], alo[2][4];
            int arow = (lane & 7) + ((lane >> 3) & 1) * 8;
            int acol = ks + (lane >> 4) * 8;
            #pragma unroll
            for (int mb = 0; mb < 2; mb++) {
                ldsm4(ahi[mb], smem_u32(&Ah[buf][wm + mb*16 + arow][acol]));
                ldsm4(alo[mb], smem_u32(&Al[buf][wm + mb*16 + arow][acol]));
            }
            u32 bhi[4][2], blo[4][2];
            int krow = ks + (lane & 7) + ((lane >> 3) & 1) * 8;
            #pragma unroll
            for (int nb = 0; nb < 4; nb++) {
                int n0 = wn + nb*8;
                ldsm2t(bhi[nb][0], bhi[nb][1], smem_u32(&Bh[buf][krow][n0]));
                ldsm2t(blo[nb][0], blo[nb][1], smem_u32(&Bl[buf][krow][n0]));
            }
            #pragma unroll
            for (int mb = 0; mb < 2; mb++)
                #pragma unroll
                for (int nb = 0; nb < 4; nb++) {
                    mma16(c[mb][nb], ahi[mb], bhi[nb]);
                    mma16(c[mb][nb], alo[mb], bhi[nb]);
                    mma16(c[mb][nb], ahi[mb], blo[nb]);
                }
        }
        __syncthreads();
    }

    int er = lane >> 2, ec = (lane & 3) * 2;
    #pragma unroll
    for (int mb = 0; mb < 2; mb++) {
        #pragma unroll
        for (int nb = 0; nb < 4; nb++) {
            int col = bn + wn + nb*8 + ec;
            float bv0 = bias ? bias[col]   : 0.0f;
            float bv1 = bias ? bias[col+1] : 0.0f;
            #pragma unroll
            for (int half = 0; half < 2; half++) {
                int rrow = bm + wm + mb*16 + er + half*8;
                size_t o = (size_t)rrow*ldc + col;
                float v0 = c[mb][nb][half*2+0] + bv0;
                float v1 = c[mb][nb][half*2+1] + bv1;
                if (ACC) { v0 += C[o]; v1 += C[o+1]; }
                if (ACT) { v0 = gelu_exact(v0); v1 = gelu_exact(v1); }
                if (C) { C[o] = v0; C[o+1] = v1; }
                if (Chi) {
                    u32 h, l;
                    split_pair(v0, v1, h, l);
                    *(u32*)(Chi + o) = h;
                    *(u32*)(Clo + o) = l;
                }
            }
        }
    }
}

template<int ACT, int ACC>
__global__ __launch_bounds__(128) void gemm64(const u16* __restrict__ Ahi,
                                              const u16* __restrict__ Alo, int lda,
                                              const u16* __restrict__ Whi,
                                              const u16* __restrict__ Wlo, int ldw,
                                              const float* __restrict__ bias,
                                              float* __restrict__ C,
                                              u16* __restrict__ Chi, u16* __restrict__ Clo,
                                              int ldc, int K) {
    gemm_bf<ACT,ACC>(Ahi, Alo, lda, Whi, Wlo, ldw, bias, C, Chi, Clo, ldc, K,
                     blockIdx.y*64, blockIdx.x*64);
}

// z-batched Pp/Qq GEMMs (A = Z planes)
__global__ __launch_bounds__(128) void pq_gemm(const u16* __restrict__ Zh, const u16* __restrict__ Zl,
                                               const u16* __restrict__ WpH, const u16* __restrict__ WpL,
                                               const u16* __restrict__ WqH, const u16* __restrict__ WqL,
                                               const float* __restrict__ bm1l,
                                               float* __restrict__ Pp,
                                               float* __restrict__ Qq) {
    if (blockIdx.z == 0)
        gemm_bf<0,0>(Zh, Zl, ZW, WpH, WpL, HH, nullptr, Pp, nullptr, nullptr, HH, 384,
                     blockIdx.y*64, blockIdx.x*64);
    else
        gemm_bf<0,0>(Zh, Zl, ZW, WqH, WqL, HH, bm1l, Qq, nullptr, nullptr, HH, 448,
                     blockIdx.y*64, blockIdx.x*64);
}

// Wmu = Wm2 @ Wu1b for both layers (z = layer)
__global__ __launch_bounds__(128) void wmu_gemm(const u16* __restrict__ Wm2H,
                                                const u16* __restrict__ Wm2L,
                                                const u16* __restrict__ Wu1bH,
                                                const u16* __restrict__ Wu1bL,
                                                float* __restrict__ Wcat) {
    int l = blockIdx.z;
    gemm_bf<0,0>(Wm2H + (size_t)l*HH*HH, Wm2L + (size_t)l*HH*HH, HH,
                 Wu1bH + (size_t)l*HH*HH, Wu1bL + (size_t)l*HH*HH, HH,
                 nullptr, Wcat + (size_t)l*2*HH*HH + (size_t)HH*HH, nullptr, nullptr,
                 HH, HH, blockIdx.y*64, blockIdx.x*64);
}

// ---------------- fused edge kernel: cat planes = [s | sum_k ew*gelu(Pp[src]+Qq)] ----------------
__global__ __launch_bounds__(256) void edge_agg_kernel(const float* __restrict__ Pp,
                                                       const float* __restrict__ Qq,
                                                       const u16* __restrict__ Zh,
                                                       const u16* __restrict__ Zl,
                                                       const int* __restrict__ Idx,
                                                       const float* __restrict__ Ew,
                                                       u16* __restrict__ CatH,
                                                       u16* __restrict__ CatL) {
    int i = blockIdx.x;
    int t = threadIdx.x;
    __shared__ int   ssrc[KNN];
    __shared__ float sw[KNN];
    if (t < KNN) { ssrc[t] = Idx[i*KNN + t]; sw[t] = Ew[i*KNN + t]; }
    __syncthreads();
    float q = Qq[i*HH + t];
    float acc = 0.0f;
    #pragma unroll
    for (int k = 0; k < KNN; k++) {
        float p = Pp[(size_t)ssrc[k]*HH + t];
        acc = fmaf(sw[k], gelu_exact(p + q), acc);
    }
    size_t ob = (size_t)i*2*HH;
    split1(acc, CatH, CatL, ob + HH + t);
    CatH[ob + t] = Zh[(size_t)i*ZW + t];
    CatL[ob + t] = Zl[(size_t)i*ZW + t];
}

// ---------------- launcher ----------------
extern "C" void kernel_launch(void* const* d_in, const int* in_sizes, int n_in,
                              void* d_out, int out_size) {
    const float* x_c   = (const float*)d_in[0];
    const float* x_d0  = (const float*)d_in[1];
    const float* x_d1  = (const float*)d_in[2];
    const float* x_d2  = (const float*)d_in[3];
    const float* x_o   = (const float*)d_in[4];
    const float* t_emb = (const float*)d_in[5];
    const float* W_in  = (const float*)d_in[6];
    const float* b_in  = (const float*)d_in[7];
    const float* Wm1   = (const float*)d_in[8];
    const float* bm1   = (const float*)d_in[9];
    const float* Wm2   = (const float*)d_in[10];
    const float* bm2   = (const float*)d_in[11];
    const float* Wu1   = (const float*)d_in[12];
    const float* bu1   = (const float*)d_in[13];
    const float* Wu2   = (const float*)d_in[14];
    const float* bu2   = (const float*)d_in[15];
    const float* W_out = (const float*)d_in[16];
    const float* b_out = (const float*)d_in[17];
    float* out = (float*)d_out;

    float *z, *dist, *ew, *pp, *qq, *wp, *wq, *wcat, *b2u, *bout;
    int* idx;
    u16 *zh, *zl, *cath, *catl, *u1h, *u1l;
    u16 *win_h, *win_l, *wp_h, *wp_l, *wq_h, *wq_l, *wcat_h, *wcat_l;
    u16 *wu2_h, *wu2_l, *wout_h, *wout_l, *wu1b_h, *wu1b_l, *wm2_h, *wm2_l;
    cudaGetSymbolAddress((void**)&z,    g_z);
    cudaGetSymbolAddress((void**)&zh,   g_zh);
    cudaGetSymbolAddress((void**)&zl,   g_zl);
    cudaGetSymbolAddress((void**)&dist, g_dist);
    cudaGetSymbolAddress((void**)&idx,  g_idx);
    cudaGetSymbolAddress((void**)&ew,   g_ew);
    cudaGetSymbolAddress((void**)&pp,   g_pp);
    cudaGetSymbolAddress((void**)&qq,   g_qq);
    cudaGetSymbolAddress((void**)&cath, g_cath);
    cudaGetSymbolAddress((void**)&catl, g_catl);
    cudaGetSymbolAddress((void**)&u1h,  g_u1h);
    cudaGetSymbolAddress((void**)&u1l,  g_u1l);
    cudaGetSymbolAddress((void**)&wp,   g_wp);
    cudaGetSymbolAddress((void**)&wq,   g_wq);
    cudaGetSymbolAddress((void**)&wcat, g_wcat);
    cudaGetSymbolAddress((void**)&b2u,  g_b2u);
    cudaGetSymbolAddress((void**)&bout, g_bout);
    cudaGetSymbolAddress((void**)&win_h,  g_win_h);  cudaGetSymbolAddress((void**)&win_l,  g_win_l);
    cudaGetSymbolAddress((void**)&wp_h,   g_wp_h);   cudaGetSymbolAddress((void**)&wp_l,   g_wp_l);
    cudaGetSymbolAddress((void**)&wq_h,   g_wq_h);   cudaGetSymbolAddress((void**)&wq_l,   g_wq_l);
    cudaGetSymbolAddress((void**)&wcat_h, g_wcat_h); cudaGetSymbolAddress((void**)&wcat_l, g_wcat_l);
    cudaGetSymbolAddress((void**)&wu2_h,  g_wu2_h);  cudaGetSymbolAddress((void**)&wu2_l,  g_wu2_l);
    cudaGetSymbolAddress((void**)&wout_h, g_wout_h); cudaGetSymbolAddress((void**)&wout_l, g_wout_l);
    cudaGetSymbolAddress((void**)&wu1b_h, g_wu1b_h); cudaGetSymbolAddress((void**)&wu1b_l, g_wu1b_l);
    cudaGetSymbolAddress((void**)&wm2_h,  g_wm2_h);  cudaGetSymbolAddress((void**)&wm2_l,  g_wm2_l);

    static cudaStream_t sB = nullptr;
    static cudaEvent_t evStart = nullptr, evZ = nullptr, evD1 = nullptr, evT1 = nullptr;
    if (sB == nullptr) {
        cudaStreamCreateWithFlags(&sB, cudaStreamNonBlocking);
        cudaEventCreateWithFlags(&evStart, cudaEventDisableTiming);
        cudaEventCreateWithFlags(&evZ,     cudaEventDisableTiming);
        cudaEventCreateWithFlags(&evD1,    cudaEventDisableTiming);
        cudaEventCreateWithFlags(&evT1,    cudaEventDisableTiming);
    }
    cudaStream_t s0 = (cudaStream_t)0;

    cudaEventRecord(evStart, s0);
    cudaStreamWaitEvent(sB, evStart, 0);

    // ---- stream A: build_z -> cdist(part1) -> cdist(part2) -> topk(rows 2048+) ----
    build_z_kernel<<<BN_, 192, 0, s0>>>(x_c, x_d0, x_d1, x_d2, x_o, t_emb, z, zh, zl);
    cudaEventRecord(evZ, s0);
    cdist_kernel<<<392, 512, 0, s0>>>(z + 256, dist, 0);     // tiles r<=15: rows [0,2048) complete
    cudaEventRecord(evD1, s0);
    cdist_kernel<<<136, 512, 0, s0>>>(z + 256, dist, 392);   // tiles r>=16: rows [2048,4096)
    topk_kernel<<<256, 256, 0, s0>>>(dist, idx, ew, 2048);

    // ---- stream B: weight prep + s-GEMM + layer-0 Pp/Qq + topk(rows 0..2047) ----
    rearrange_w_kernel<<<(NL*1088*HH)/256, 256, 0, sB>>>(Wm1, Wu1, wp, wq, wcat);
    bias_u1_kernel<<<NL, 256, 0, sB>>>(bm2, bu1, Wu1, b2u);
    bout_kernel<<<1, DD, 0, sB>>>(b_out, bout);
    wsplit_all_kernel<<<(SP6 + 255)/256, 256, 0, sB>>>(W_in, wp, wq, Wu2, W_out, Wu1, Wm2,
                                                       win_h, win_l, wp_h, wp_l, wq_h, wq_l,
                                                       wu2_h, wu2_l, wout_h, wout_l,
                                                       wu1b_h, wu1b_l, wm2_h, wm2_l);
    wmu_gemm<<<dim3(4,4,NL), 128, 0, sB>>>(wm2_h, wm2_l, wu1b_h, wu1b_l, wcat);
    wsplit_kernel<<<(NL*2*HH*HH + 255)/256, 256, 0, sB>>>(wcat, wcat_h, wcat_l, NL*2*HH*HH);

    dim3 gB(HH/64, BN_/64);
    dim3 gPQ(HH/64, BN_/64, 2);
    dim3 gO(DD/64, BN_/64);

    cudaStreamWaitEvent(sB, evZ, 0);
    // s = x @ W_in + b_in  -> Z[:, 0:256] fp32 + planes
    gemm64<0,0><<<gB, 128, 0, sB>>>(zh + 256, zl + 256, ZW, win_h, win_l, HH,
                                    b_in, z, zh, zl, ZW, DD);
    // layer-0 Pp/Qq (independent of topk)
    pq_gemm<<<gPQ, 128, 0, sB>>>(zh, zl, wp_h, wp_l, wq_h, wq_l, bm1, pp, qq);
    // topk for rows [0,2048): dist half 1 ready after evD1; overlaps cdist part2 on s0
    cudaStreamWaitEvent(sB, evD1, 0);
    topk_kernel<<<256, 256, 0, sB>>>(dist, idx, ew, 0);
    cudaEventRecord(evT1, sB);

    // ---- join: stream A continues the serial tail ----
    cudaStreamWaitEvent(s0, evT1, 0);

    for (int l = 0; l < NL; l++) {
        const u16* wch = wcat_h + (size_t)l * 2*HH * HH;
        const u16* wcl = wcat_l + (size_t)l * 2*HH * HH;
        const u16* w2h = wu2_h + (size_t)l * HH * HH;
        const u16* w2l = wu2_l + (size_t)l * HH * HH;

        if (l > 0) {
            const u16* wph = wp_h + (size_t)l * 384 * HH;
            const u16* wpl = wp_l + (size_t)l * 384 * HH;
            const u16* wqh = wq_h + (size_t)l * 448 * HH;
            const u16* wql = wq_l + (size_t)l * 448 * HH;
            pq_gemm<<<gPQ, 128, 0, s0>>>(zh, zl, wph, wpl, wqh, wql, bm1 + l*HH, pp, qq);
        }
        // cat planes = [s | sum_k ew*gelu(Pp[src]+Qq[i])]
        edge_agg_kernel<<<BN_, 256, 0, s0>>>(pp, qq, zh, zl, idx, ew, cath, catl);
        // u1 = gelu(cat @ [Wu1a; Wm2@Wu1b] + b2u) -> planes only
        gemm64<1,0><<<gB, 128, 0, s0>>>(cath, catl, 2*HH, wch, wcl, HH,
                                        b2u + l*HH, nullptr, u1h, u1l, HH, 2*HH);
        // s += u1 @ Wu2 + bu2  (fp32 z + planes)
        gemm64<0,1><<<gB, 128, 0, s0>>>(u1h, u1l, HH, w2h, w2l, HH,
                                        bu2 + l*HH, z, zh, zl, ZW, HH);
    }

    // out = s @ W_out' + b_out'  (centering folded into weights) -> d_out directly
    gemm64<0,0><<<gO, 128, 0, s0>>>(zh, zl, ZW, wout_h, wout_l, DD,
                                    bout, out, nullptr, nullptr, DD, HH);
}

// round 15
// speedup vs baseline: 1.0275x; 1.0275x over previous
#include <cuda_runtime.h>
#include <cuda_bf16.h>
#include <math.h>

#define BN_ 4096      // batch
#define DD  128       // feature dim
#define HH  256       // hidden
#define TT  64        // time emb
#define KNN 10
#define NL  2
#define ZW  448       // Z row width: [s(256) | x(128) | t(64)]

typedef unsigned long long u64;
typedef unsigned int u32;
typedef unsigned short u16;

// ---------------- static scratch ----------------
__device__ __align__(128) float g_z[BN_*ZW];             // [s | x | t] fp32
__device__ __align__(128) u16   g_zh[BN_*ZW], g_zl[BN_*ZW];      // bf16 planes of Z
__device__ __align__(128) float g_dist[(size_t)BN_*BN_]; // 64 MB
__device__ __align__(128) int   g_idx[BN_*KNN];
__device__ __align__(128) float g_ew[BN_*KNN];
__device__ __align__(128) float g_pp[BN_*HH];
__device__ __align__(128) float g_qq[BN_*HH];
__device__ __align__(128) u16   g_cath[BN_*2*HH], g_catl[BN_*2*HH];
__device__ __align__(128) u16   g_u1h[BN_*HH],    g_u1l[BN_*HH];
__device__ __align__(128) float g_wp[NL*384*HH];         // [W1a; W1c] fp32 staging
__device__ __align__(128) float g_wq[NL*448*HH];         // [W1b; -W1c; W1d] fp32 staging
__device__ __align__(128) float g_wcat[NL*2*HH*HH];      // [Wu1a; Wm2@Wu1b] fp32 staging
__device__ __align__(128) float g_b2u[NL*HH];            // bm2@Wu1b + bu1
__device__ __align__(128) float g_bout[DD];              // centered b_out
// pre-split bf16 weight planes
__device__ __align__(128) u16 g_win_h[DD*HH],        g_win_l[DD*HH];
__device__ __align__(128) u16 g_wp_h[NL*384*HH],     g_wp_l[NL*384*HH];
__device__ __align__(128) u16 g_wq_h[NL*448*HH],     g_wq_l[NL*448*HH];
__device__ __align__(128) u16 g_wcat_h[NL*2*HH*HH],  g_wcat_l[NL*2*HH*HH];
__device__ __align__(128) u16 g_wu2_h[NL*HH*HH],     g_wu2_l[NL*HH*HH];
__device__ __align__(128) u16 g_wout_h[HH*DD],       g_wout_l[HH*DD];
__device__ __align__(128) u16 g_wu1b_h[NL*HH*HH],    g_wu1b_l[NL*HH*HH];
__device__ __align__(128) u16 g_wm2_h[NL*HH*HH],     g_wm2_l[NL*HH*HH];

__device__ __forceinline__ float gelu_exact(float x) {
    return 0.5f * x * (1.0f + erff(x * 0.70710678118654752440f));
}

__device__ __forceinline__ u64 pack_f2(float x, float y) {
    u64 r; asm("mov.b64 %0, {%1, %2};" : "=l"(r) : "f"(x), "f"(y)); return r;
}
__device__ __forceinline__ float2 unpack_f2(u64 v) {
    float2 f; asm("mov.b64 {%0, %1}, %2;" : "=f"(f.x), "=f"(f.y) : "l"(v)); return f;
}
__device__ __forceinline__ void l1_acc(u64& acc, u64 a, u64 nb) {
    u64 d;
    asm("add.rn.f32x2 %0, %1, %2;" : "=l"(d) : "l"(a), "l"(nb));
    u32 lo = (u32)d & 0x7fffffffu;
    u32 hi = (u32)(d >> 32) & 0x7fffffffu;
    u64 m = ((u64)hi << 32) | (u64)lo;
    asm("add.rn.f32x2 %0, %0, %1;" : "+l"(acc) : "l"(m));
}

// ---------------- bf16 helpers ----------------
__device__ __forceinline__ void split_pair(float x0, float x1, u32& hi, u32& lo) {
    asm("cvt.rn.bf16x2.f32 %0, %1, %2;" : "=r"(hi) : "f"(x1), "f"(x0));
    float h0 = __uint_as_float(hi << 16);
    float h1 = __uint_as_float(hi & 0xffff0000u);
    float l0 = x0 - h0, l1 = x1 - h1;
    asm("cvt.rn.bf16x2.f32 %0, %1, %2;" : "=r"(lo) : "f"(l1), "f"(l0));
}
__device__ __forceinline__ void mma16(float* c, const u32* a, const u32* b) {
    asm volatile("mma.sync.aligned.m16n8k16.row.col.f32.bf16.bf16.f32 "
                 "{%0,%1,%2,%3}, {%4,%5,%6,%7}, {%8,%9}, {%0,%1,%2,%3};"
                 : "+f"(c[0]), "+f"(c[1]), "+f"(c[2]), "+f"(c[3])
                 : "r"(a[0]), "r"(a[1]), "r"(a[2]), "r"(a[3]),
                   "r"(b[0]), "r"(b[1]));
}
__device__ __forceinline__ void ldsm2t(u32& r0, u32& r1, u32 addr) {
    asm volatile("ldmatrix.sync.aligned.m8n8.x2.trans.shared.b16 {%0,%1}, [%2];"
                 : "=r"(r0), "=r"(r1) : "r"(addr));
}
__device__ __forceinline__ void ldsm4(u32* r, u32 addr) {
    asm volatile("ldmatrix.sync.aligned.m8n8.x4.shared.b16 {%0,%1,%2,%3}, [%4];"
                 : "=r"(r[0]), "=r"(r[1]), "=r"(r[2]), "=r"(r[3]) : "r"(addr));
}
__device__ __forceinline__ u32 smem_u32(const void* p) {
    return (u32)__cvta_generic_to_shared(p);
}
__device__ __forceinline__ void cp16(u32 dst, const void* src) {
    asm volatile("cp.async.cg.shared.global [%0], [%1], 16;\n" :: "r"(dst), "l"(src));
}
__device__ __forceinline__ void split1(float x, u16* hi, u16* lo, size_t i) {
    __nv_bfloat16 h = __float2bfloat16_rn(x);
    float hf = __bfloat162float(h);
    __nv_bfloat16 l = __float2bfloat16_rn(x - hf);
    hi[i] = *(u16*)&h;
    lo[i] = *(u16*)&l;
}

// ---------------- build Z = [s(later) | x | t] + planes ----------------
__global__ void build_z_kernel(const float* __restrict__ xc, const float* __restrict__ d0,
                               const float* __restrict__ d1, const float* __restrict__ d2,
                               const float* __restrict__ xo, const float* __restrict__ te,
                               float* __restrict__ Z, u16* __restrict__ Zh, u16* __restrict__ Zl) {
    int i = blockIdx.x;
    int t = threadIdx.x; // 192
    float v; int c;
    if (t < 128) {
        if (t < 64)       v = xc[i*64 + t];
        else if (t < 80)  v = d0[i*16 + (t-64)];
        else if (t < 96)  v = d1[i*16 + (t-80)];
        else if (t < 112) v = d2[i*16 + (t-96)];
        else              v = xo[i*16 + (t-112)];
        c = 256 + t;
    } else {
        v = te[i*TT + (t-128)];
        c = 384 + (t-128);
    }
    size_t o = (size_t)i*ZW + c;
    Z[o] = v;
    split1(v, Zh, Zl, o);
}

// ---------------- rearranged weights (fp32 staging) ----------------
__global__ void rearrange_w_kernel(const float* __restrict__ Wm1,
                                   const float* __restrict__ Wu1,
                                   float* __restrict__ Wp, float* __restrict__ Wq,
                                   float* __restrict__ Wcat) {
    int idx = blockIdx.x * 256 + threadIdx.x;
    int l = idx / (1088*HH);
    int r2 = idx - l*(1088*HH);
    int r = r2 / HH, c = r2 - (r2/HH)*HH;
    const float* w = Wm1 + (size_t)l*704*HH;
    if (r < 384) {
        int sr = (r < 256) ? r : (512 + (r - 256));
        Wp[(size_t)l*384*HH + r*HH + c] = w[sr*HH + c];
    } else if (r < 832) {
        int rq = r - 384;
        float sgn = 1.0f; int sr;
        if (rq < 256)      sr = 256 + rq;
        else if (rq < 384) { sr = 512 + (rq - 256); sgn = -1.0f; }
        else               sr = 640 + (rq - 384);
        Wq[(size_t)l*448*HH + rq*HH + c] = sgn * w[sr*HH + c];
    } else {
        int rc = r - 832;
        Wcat[(size_t)l*2*HH*HH + rc*HH + c] = Wu1[(size_t)l*2*HH*HH + rc*HH + c];
    }
}

// ---------------- fold bias: b2u = bm2 @ Wu1b + bu1 ----------------
__global__ void bias_u1_kernel(const float* __restrict__ bm2, const float* __restrict__ bu1,
                               const float* __restrict__ Wu1, float* __restrict__ b2u) {
    int l = blockIdx.x;
    int c = threadIdx.x;
    const float* wb = Wu1 + (size_t)l*2*HH*HH + (size_t)HH*HH;
    float acc = bu1[l*HH + c];
    for (int k = 0; k < HH; k++) acc = fmaf(bm2[l*HH + k], wb[k*HH + c], acc);
    b2u[l*HH + c] = acc;
}

// ---------------- centered b_out ----------------
__global__ void bout_kernel(const float* __restrict__ b_out, float* __restrict__ bout_c) {
    int c = threadIdx.x; // 128
    float v = b_out[c];
    if (c >= 64 && c < 112) {
        int blk = 64 + (((c - 64) >> 4) << 4);
        float m = 0.0f;
        #pragma unroll
        for (int q = 0; q < 16; q++) m += b_out[blk + q];
        v -= m * (1.0f/16.0f);
    }
    bout_c[c] = v;
}

// one launch for all independent weight splits (W_out centered on the fly)
#define SP0 (DD*HH)
#define SP1 (SP0 + NL*384*HH)
#define SP2 (SP1 + NL*448*HH)
#define SP3 (SP2 + NL*HH*HH)
#define SP4 (SP3 + HH*DD)
#define SP5 (SP4 + NL*HH*HH)
#define SP6 (SP5 + NL*HH*HH)
__global__ void wsplit_all_kernel(const float* __restrict__ W_in,
                                  const float* __restrict__ wp,
                                  const float* __restrict__ wq,
                                  const float* __restrict__ Wu2,
                                  const float* __restrict__ W_out,
                                  const float* __restrict__ Wu1,
                                  const float* __restrict__ Wm2,
                                  u16* win_h, u16* win_l, u16* wp_h, u16* wp_l,
                                  u16* wq_h, u16* wq_l, u16* wu2_h, u16* wu2_l,
                                  u16* wout_h, u16* wout_l, u16* wu1b_h, u16* wu1b_l,
                                  u16* wm2_h, u16* wm2_l) {
    int i = blockIdx.x * 256 + threadIdx.x;
    if (i < SP0) {
        split1(W_in[i], win_h, win_l, i);
    } else if (i < SP1) {
        int j = i - SP0; split1(wp[j], wp_h, wp_l, j);
    } else if (i < SP2) {
        int j = i - SP1; split1(wq[j], wq_h, wq_l, j);
    } else if (i < SP3) {
        int j = i - SP2; split1(Wu2[j], wu2_h, wu2_l, j);
    } else if (i < SP4) {
        int j = i - SP3;                 // r*DD + c
        int c = j & (DD-1);
        float v = W_out[j];
        if (c >= 64 && c < 112) {        // center categorical blocks (exact linear fold)
            int blk = j - c + 64 + (((c - 64) >> 4) << 4);
            float m = 0.0f;
            #pragma unroll
            for (int q = 0; q < 16; q++) m += W_out[blk + q];
            v -= m * (1.0f/16.0f);
        }
        split1(v, wout_h, wout_l, j);
    } else if (i < SP5) {
        int j = i - SP4;
        int l = j >> 16;
        int e = j & 65535;
        split1(Wu1[(size_t)l*2*HH*HH + (size_t)HH*HH + e], wu1b_h, wu1b_l, j);
    } else if (i < SP6) {
        int j = i - SP5; split1(Wm2[j], wm2_h, wm2_l, j);
    }
}

__global__ void wsplit_kernel(const float* __restrict__ src, u16* __restrict__ hi,
                              u16* __restrict__ lo, int n) {
    int i = blockIdx.x * 256 + threadIdx.x;
    if (i >= n) return;
    split1(src[i], hi, lo, i);
}

// ---------------- symmetric L1 cdist, 128x128 tiles, conflict-free B layout ----------------
__global__ __launch_bounds__(512) void cdist_kernel(const float* __restrict__ X,
                                                    float* __restrict__ Dist) {
    __shared__ u64 As2[16][128];
    __shared__ u64 Bs2[4][17][33];   // [j][kk][col], lanes read consecutive u64 -> conflict-free
    int r = 0, rem = blockIdx.x;
    while (rem >= 32 - r) { rem -= 32 - r; r++; }
    int bm = r * 128, bn = (r + rem) * 128;

    int tid = threadIdx.x;
    int ty = tid >> 5;
    int tx = tid & 31;
    u64 acc2[8][4];
    #pragma unroll
    for (int i = 0; i < 8; i++)
        #pragma unroll
        for (int j = 0; j < 4; j++) acc2[i][j] = 0ull;

    int lrow = tid >> 2;
    int lq   = (tid & 3) * 8;
    int jb = lrow & 3, cb = lrow >> 2;
    int ks = lq >> 1;          // (tid&3)*4

    for (int k0 = 0; k0 < DD; k0 += 32) {
        float4 va0 = *(const float4*)&X[(size_t)(bm + lrow)*ZW + k0 + lq];
        float4 va1 = *(const float4*)&X[(size_t)(bm + lrow)*ZW + k0 + lq + 4];
        As2[ks+0][lrow] = pack_f2(va0.x, va0.y);
        As2[ks+1][lrow] = pack_f2(va0.z, va0.w);
        As2[ks+2][lrow] = pack_f2(va1.x, va1.y);
        As2[ks+3][lrow] = pack_f2(va1.z, va1.w);
        float4 vb0 = *(const float4*)&X[(size_t)(bn + lrow)*ZW + k0 + lq];
        float4 vb1 = *(const float4*)&X[(size_t)(bn + lrow)*ZW + k0 + lq + 4];
        Bs2[jb][ks+0][cb] = pack_f2(-vb0.x, -vb0.y);
        Bs2[jb][ks+1][cb] = pack_f2(-vb0.z, -vb0.w);
        Bs2[jb][ks+2][cb] = pack_f2(-vb1.x, -vb1.y);
        Bs2[jb][ks+3][cb] = pack_f2(-vb1.z, -vb1.w);
        __syncthreads();
        #pragma unroll
        for (int kk = 0; kk < 16; kk++) {
            u64 a2[8], b2[4];
            #pragma unroll
            for (int i = 0; i < 8; i++) a2[i] = As2[kk][ty*8 + i];
            #pragma unroll
            for (int j = 0; j < 4; j++) b2[j] = Bs2[j][kk][tx];
            #pragma unroll
            for (int i = 0; i < 8; i++)
                #pragma unroll
                for (int j = 0; j < 4; j++) l1_acc(acc2[i][j], a2[i], b2[j]);
        }
        __syncthreads();
    }
    float res[8][4];
    #pragma unroll
    for (int i = 0; i < 8; i++)
        #pragma unroll
        for (int j = 0; j < 4; j++) {
            float2 f = unpack_f2(acc2[i][j]);
            res[i][j] = f.x + f.y;
        }
    if (bm == bn) {
        #pragma unroll
        for (int i = 0; i < 8; i++)
            #pragma unroll
            for (int j = 0; j < 4; j++)
                if (ty*8 + i == tx*4 + j) res[i][j] = __int_as_float(0x7f800000);
    }
    #pragma unroll
    for (int i = 0; i < 8; i++) {
        float4 v = make_float4(res[i][0], res[i][1], res[i][2], res[i][3]);
        *(float4*)&Dist[(size_t)(bm + ty*8 + i)*BN_ + bn + tx*4] = v;
    }
    if (bm != bn) {
        #pragma unroll
        for (int j = 0; j < 4; j++) {
            float4 v0 = make_float4(res[0][j], res[1][j], res[2][j], res[3][j]);
            float4 v1 = make_float4(res[4][j], res[5][j], res[6][j], res[7][j]);
            size_t o = (size_t)(bn + tx*4 + j)*BN_ + bm + ty*8;
            *(float4*)&Dist[o]     = v0;
            *(float4*)&Dist[o + 4] = v1;
        }
    }
}

// ---------------- top-K: warp per row, 2-pass with provable prefilter ----------------
__global__ __launch_bounds__(256) void topk_kernel(const float* __restrict__ Dist,
                                                   int* __restrict__ Idx,
                                                   float* __restrict__ Ew) {
    __shared__ float sdm[8][32*KNN];
    __shared__ int   sim[8][32*KNN];
    int warp = threadIdx.x >> 5;
    int lane = threadIdx.x & 31;
    int i = blockIdx.x * 8 + warp;
    const float4* row = (const float4*)(Dist + (size_t)i * BN_);
    const float INF = __int_as_float(0x7f800000);

    float mn = INF;
    #pragma unroll 4
    for (int it = 0; it < 32; it++) {
        float4 d4 = row[it*32 + lane];
        mn = fminf(mn, fminf(fminf(d4.x, d4.y), fminf(d4.z, d4.w)));
    }
    float cur = mn, T = INF;
    #pragma unroll
    for (int q = 0; q < KNN; q++) {
        float wmin = cur;
        #pragma unroll
        for (int off = 16; off >= 1; off >>= 1)
            wmin = fminf(wmin, __shfl_xor_sync(0xffffffffu, wmin, off));
        T = wmin;
        u32 ballot = __ballot_sync(0xffffffffu, cur == wmin);
        int first = __ffs(ballot) - 1;
        if (lane == first) cur = INF;
    }

    float bd[KNN]; int bi[KNN];
    #pragma unroll
    for (int q = 0; q < KNN; q++) { bd[q] = INF; bi[q] = 0x7fffffff; }
    #pragma unroll 4
    for (int it = 0; it < 32; it++) {
        int jv = it*32 + lane;
        float4 d4 = row[jv];
        float dv[4] = {d4.x, d4.y, d4.z, d4.w};
        #pragma unroll
        for (int q4 = 0; q4 < 4; q4++) {
            float d = dv[q4];
            if (d <= T) {
                float dd = d; int ii = jv*4 + q4;
                #pragma unroll
                for (int q = 0; q < KNN; q++) {
                    bool c = dd < bd[q];
                    float tf = bd[q]; int ti = bi[q];
                    bd[q] = c ? dd : bd[q]; bi[q] = c ? ii : bi[q];
                    dd = c ? tf : dd;       ii = c ? ti : ii;
                }
            }
        }
    }

    float* sdw = sdm[warp];
    int*   siw = sim[warp];
    #pragma unroll
    for (int q = 0; q < KNN; q++) { sdw[lane*KNN + q] = bd[q]; siw[lane*KNN + q] = bi[q]; }
    __syncwarp();
    #pragma unroll
    for (int stride = 1; stride < 32; stride <<= 1) {
        if ((lane & (2*stride - 1)) == 0) {
            float* da = sdw + lane*KNN;            int* ia = siw + lane*KNN;
            float* db = sdw + (lane+stride)*KNN;   int* ib = siw + (lane+stride)*KNN;
            float od[KNN]; int oi[KNN];
            int pa = 0, pb = 0;
            #pragma unroll
            for (int q = 0; q < KNN; q++) {
                float va = da[pa], vb = db[pb];
                bool c = va <= vb;
                od[q] = c ? va : vb;
                oi[q] = c ? ia[pa] : ib[pb];
                pa += c; pb += !c;
            }
            #pragma unroll
            for (int q = 0; q < KNN; q++) { da[q] = od[q]; ia[q] = oi[q]; }
        }
        __syncwarp();
    }

    if (lane == 0) {
        float d[KNN]; int ix[KNN];
        #pragma unroll
        for (int q = 0; q < KNN; q++) { d[q] = sdw[q]; ix[q] = siw[q]; }
        float w[KNN], sum = 0.0f;
        float dmin = d[0];
        #pragma unroll
        for (int q = 0; q < KNN; q++) { w[q] = expf(dmin - d[q]); sum += w[q]; }
        float inv = 1.0f / sum;
        #pragma unroll
        for (int q = 0; q < KNN; q++) {
            Ew[i*KNN + q] = w[q] * inv;
            Idx[i*KNN + q] = ix[q];
        }
    }
}

// ---- bf16 tensor-core GEMM: pre-split A AND B planes, pure-ldmatrix mainloop ----
template<int ACT, int ACC>
__device__ __forceinline__ void gemm_bf(const u16* __restrict__ Ahi_g,
                                        const u16* __restrict__ Alo_g, int lda,
                                        const u16* __restrict__ Whi,
                                        const u16* __restrict__ Wlo, int ldw,
                                        const float* __restrict__ bias,
                                        float* __restrict__ C,
                                        u16* __restrict__ Chi, u16* __restrict__ Clo,
                                        int ldc, int K, int bm, int bn) {
    __shared__ alignas(16) u16 Ah[2][64][40];
    __shared__ alignas(16) u16 Al[2][64][40];
    __shared__ alignas(16) u16 Bh[2][32][72];
    __shared__ alignas(16) u16 Bl[2][32][72];
    int tid = threadIdx.x, lane = tid & 31, wid = tid >> 5;
    int wm = (wid >> 1) * 32, wn = (wid & 1) * 32;
    float c[2][4][4];
    #pragma unroll
    for (int mb = 0; mb < 2; mb++)
        #pragma unroll
        for (int nb = 0; nb < 4; nb++)
            #pragma unroll
            for (int q = 0; q < 4; q++) c[mb][nb][q] = 0.0f;

    int as0 = tid, as1 = tid + 128;
    int ar0 = as0 >> 2, ao0 = (as0 & 3) * 8;
    int ar1 = as1 >> 2, ao1 = (as1 & 3) * 8;
    int brow = tid >> 2, bcol = (tid & 3) * 16;

    const u16* ah0 = &Ahi_g[(size_t)(bm + ar0)*lda + ao0];
    const u16* ah1 = &Ahi_g[(size_t)(bm + ar1)*lda + ao1];
    const u16* al0 = &Alo_g[(size_t)(bm + ar0)*lda + ao0];
    const u16* al1 = &Alo_g[(size_t)(bm + ar1)*lda + ao1];
    const u16* bh0 = &Whi[(size_t)brow*ldw + bn + bcol];
    const u16* bl0 = &Wlo[(size_t)brow*ldw + bn + bcol];

    {
        cp16(smem_u32(&Ah[0][ar0][ao0]), ah0);
        cp16(smem_u32(&Ah[0][ar1][ao1]), ah1);
        cp16(smem_u32(&Al[0][ar0][ao0]), al0);
        cp16(smem_u32(&Al[0][ar1][ao1]), al1);
        u32 dh = smem_u32(&Bh[0][brow][bcol]);
        cp16(dh, bh0); cp16(dh+16, bh0+8);
        u32 dl = smem_u32(&Bl[0][brow][bcol]);
        cp16(dl, bl0); cp16(dl+16, bl0+8);
        asm volatile("cp.async.commit_group;\n");
    }

    int nch = K >> 5;
    for (int ch = 0; ch < nch; ch++) {
        int buf = ch & 1;
        if (ch + 1 < nch) {
            int k0 = (ch + 1) * 32;
            cp16(smem_u32(&Ah[buf^1][ar0][ao0]), ah0 + k0);
            cp16(smem_u32(&Ah[buf^1][ar1][ao1]), ah1 + k0);
            cp16(smem_u32(&Al[buf^1][ar0][ao0]), al0 + k0);
            cp16(smem_u32(&Al[buf^1][ar1][ao1]), al1 + k0);
            u32 dh = smem_u32(&Bh[buf^1][brow][bcol]);
            const u16* sh = bh0 + (size_t)k0*ldw;
            cp16(dh, sh); cp16(dh+16, sh+8);
            u32 dl = smem_u32(&Bl[buf^1][brow][bcol]);
            const u16* sl = bl0 + (size_t)k0*ldw;
            cp16(dl, sl); cp16(dl+16, sl+8);
            asm volatile("cp.async.commit_group;\n");
            asm volatile("cp.async.wait_group 1;\n");
        } else {
            asm volatile("cp.async.wait_group 0;\n");
        }
        __syncthreads();
        #pragma unroll
        for (int ks = 0; ks < 32; ks += 16) {
            u32 ahi[2][4], alo[2][4];
            int arow = (lane & 7) + ((lane >> 3) & 1) * 8;
            int acol = ks + (lane >> 4) * 8;
            #pragma unroll
            for (int mb = 0; mb < 2; mb++) {
                ldsm4(ahi[mb], smem_u32(&Ah[buf][wm + mb*16 + arow][acol]));
                ldsm4(alo[mb], smem_u32(&Al[buf][wm + mb*16 + arow][acol]));
            }
            u32 bhi[4][2], blo[4][2];
            int krow = ks + (lane & 7) + ((lane >> 3) & 1) * 8;
            #pragma unroll
            for (int nb = 0; nb < 4; nb++) {
                int n0 = wn + nb*8;
                ldsm2t(bhi[nb][0], bhi[nb][1], smem_u32(&Bh[buf][krow][n0]));
                ldsm2t(blo[nb][0], blo[nb][1], smem_u32(&Bl[buf][krow][n0]));
            }
            #pragma unroll
            for (int mb = 0; mb < 2; mb++)
                #pragma unroll
                for (int nb = 0; nb < 4; nb++) {
                    mma16(c[mb][nb], ahi[mb], bhi[nb]);
                    mma16(c[mb][nb], alo[mb], bhi[nb]);
                    mma16(c[mb][nb], ahi[mb], blo[nb]);
                }
        }
        __syncthreads();
    }

    int er = lane >> 2, ec = (lane & 3) * 2;
    #pragma unroll
    for (int mb = 0; mb < 2; mb++) {
        #pragma unroll
        for (int nb = 0; nb < 4; nb++) {
            int col = bn + wn + nb*8 + ec;
            float bv0 = bias ? bias[col]   : 0.0f;
            float bv1 = bias ? bias[col+1] : 0.0f;
            #pragma unroll
            for (int half = 0; half < 2; half++) {
                int rrow = bm + wm + mb*16 + er + half*8;
                size_t o = (size_t)rrow*ldc + col;
                float v0 = c[mb][nb][half*2+0] + bv0;
                float v1 = c[mb][nb][half*2+1] + bv1;
                if (ACC) { v0 += C[o]; v1 += C[o+1]; }
                if (ACT) { v0 = gelu_exact(v0); v1 = gelu_exact(v1); }
                if (C) { C[o] = v0; C[o+1] = v1; }
                if (Chi) {
                    u32 h, l;
                    split_pair(v0, v1, h, l);
                    *(u32*)(Chi + o) = h;
                    *(u32*)(Clo + o) = l;
                }
            }
        }
    }
}

template<int ACT, int ACC>
__global__ __launch_bounds__(128) void gemm64(const u16* __restrict__ Ahi,
                                              const u16* __restrict__ Alo, int lda,
                                              const u16* __restrict__ Whi,
                                              const u16* __restrict__ Wlo, int ldw,
                                              const float* __restrict__ bias,
                                              float* __restrict__ C,
                                              u16* __restrict__ Chi, u16* __restrict__ Clo,
                                              int ldc, int K) {
    gemm_bf<ACT,ACC>(Ahi, Alo, lda, Whi, Wlo, ldw, bias, C, Chi, Clo, ldc, K,
                     blockIdx.y*64, blockIdx.x*64);
}

// z-batched Pp/Qq GEMMs (A = Z planes)
__global__ __launch_bounds__(128) void pq_gemm(const u16* __restrict__ Zh, const u16* __restrict__ Zl,
                                               const u16* __restrict__ WpH, const u16* __restrict__ WpL,
                                               const u16* __restrict__ WqH, const u16* __restrict__ WqL,
                                               const float* __restrict__ bm1l,
                                               float* __restrict__ Pp,
                                               float* __restrict__ Qq) {
    if (blockIdx.z == 0)
        gemm_bf<0,0>(Zh, Zl, ZW, WpH, WpL, HH, nullptr, Pp, nullptr, nullptr, HH, 384,
                     blockIdx.y*64, blockIdx.x*64);
    else
        gemm_bf<0,0>(Zh, Zl, ZW, WqH, WqL, HH, bm1l, Qq, nullptr, nullptr, HH, 448,
                     blockIdx.y*64, blockIdx.x*64);
}

// Wmu = Wm2 @ Wu1b for both layers (z = layer)
__global__ __launch_bounds__(128) void wmu_gemm(const u16* __restrict__ Wm2H,
                                                const u16* __restrict__ Wm2L,
                                                const u16* __restrict__ Wu1bH,
                                                const u16* __restrict__ Wu1bL,
                                                float* __restrict__ Wcat) {
    int l = blockIdx.z;
    gemm_bf<0,0>(Wm2H + (size_t)l*HH*HH, Wm2L + (size_t)l*HH*HH, HH,
                 Wu1bH + (size_t)l*HH*HH, Wu1bL + (size_t)l*HH*HH, HH,
                 nullptr, Wcat + (size_t)l*2*HH*HH + (size_t)HH*HH, nullptr, nullptr,
                 HH, HH, blockIdx.y*64, blockIdx.x*64);
}

// ---------------- fused edge kernel: cat planes = [s | sum_k ew*gelu(Pp[src]+Qq)] ----------------
__global__ __launch_bounds__(256) void edge_agg_kernel(const float* __restrict__ Pp,
                                                       const float* __restrict__ Qq,
                                                       const u16* __restrict__ Zh,
                                                       const u16* __restrict__ Zl,
                                                       const int* __restrict__ Idx,
                                                       const float* __restrict__ Ew,
                                                       u16* __restrict__ CatH,
                                                       u16* __restrict__ CatL) {
    int i = blockIdx.x;
    int t = threadIdx.x;
    __shared__ int   ssrc[KNN];
    __shared__ float sw[KNN];
    if (t < KNN) { ssrc[t] = Idx[i*KNN + t]; sw[t] = Ew[i*KNN + t]; }
    __syncthreads();
    float q = Qq[i*HH + t];
    float acc = 0.0f;
    #pragma unroll
    for (int k = 0; k < KNN; k++) {
        float p = Pp[(size_t)ssrc[k]*HH + t];
        acc = fmaf(sw[k], gelu_exact(p + q), acc);
    }
    size_t ob = (size_t)i*2*HH;
    split1(acc, CatH, CatL, ob + HH + t);
    CatH[ob + t] = Zh[(size_t)i*ZW + t];
    CatL[ob + t] = Zl[(size_t)i*ZW + t];
}

// ---------------- launcher ----------------
extern "C" void kernel_launch(void* const* d_in, const int* in_sizes, int n_in,
                              void* d_out, int out_size) {
    const float* x_c   = (const float*)d_in[0];
    const float* x_d0  = (const float*)d_in[1];
    const float* x_d1  = (const float*)d_in[2];
    const float* x_d2  = (const float*)d_in[3];
    const float* x_o   = (const float*)d_in[4];
    const float* t_emb = (const float*)d_in[5];
    const float* W_in  = (const float*)d_in[6];
    const float* b_in  = (const float*)d_in[7];
    const float* Wm1   = (const float*)d_in[8];
    const float* bm1   = (const float*)d_in[9];
    const float* Wm2   = (const float*)d_in[10];
    const float* bm2   = (const float*)d_in[11];
    const float* Wu1   = (const float*)d_in[12];
    const float* bu1   = (const float*)d_in[13];
    const float* Wu2   = (const float*)d_in[14];
    const float* bu2   = (const float*)d_in[15];
    const float* W_out = (const float*)d_in[16];
    const float* b_out = (const float*)d_in[17];
    float* out = (float*)d_out;

    float *z, *dist, *ew, *pp, *qq, *wp, *wq, *wcat, *b2u, *bout;
    int* idx;
    u16 *zh, *zl, *cath, *catl, *u1h, *u1l;
    u16 *win_h, *win_l, *wp_h, *wp_l, *wq_h, *wq_l, *wcat_h, *wcat_l;
    u16 *wu2_h, *wu2_l, *wout_h, *wout_l, *wu1b_h, *wu1b_l, *wm2_h, *wm2_l;
    cudaGetSymbolAddress((void**)&z,    g_z);
    cudaGetSymbolAddress((void**)&zh,   g_zh);
    cudaGetSymbolAddress((void**)&zl,   g_zl);
    cudaGetSymbolAddress((void**)&dist, g_dist);
    cudaGetSymbolAddress((void**)&idx,  g_idx);
    cudaGetSymbolAddress((void**)&ew,   g_ew);
    cudaGetSymbolAddress((void**)&pp,   g_pp);
    cudaGetSymbolAddress((void**)&qq,   g_qq);
    cudaGetSymbolAddress((void**)&cath, g_cath);
    cudaGetSymbolAddress((void**)&catl, g_catl);
    cudaGetSymbolAddress((void**)&u1h,  g_u1h);
    cudaGetSymbolAddress((void**)&u1l,  g_u1l);
    cudaGetSymbolAddress((void**)&wp,   g_wp);
    cudaGetSymbolAddress((void**)&wq,   g_wq);
    cudaGetSymbolAddress((void**)&wcat, g_wcat);
    cudaGetSymbolAddress((void**)&b2u,  g_b2u);
    cudaGetSymbolAddress((void**)&bout, g_bout);
    cudaGetSymbolAddress((void**)&win_h,  g_win_h);  cudaGetSymbolAddress((void**)&win_l,  g_win_l);
    cudaGetSymbolAddress((void**)&wp_h,   g_wp_h);   cudaGetSymbolAddress((void**)&wp_l,   g_wp_l);
    cudaGetSymbolAddress((void**)&wq_h,   g_wq_h);   cudaGetSymbolAddress((void**)&wq_l,   g_wq_l);
    cudaGetSymbolAddress((void**)&wcat_h, g_wcat_h); cudaGetSymbolAddress((void**)&wcat_l, g_wcat_l);
    cudaGetSymbolAddress((void**)&wu2_h,  g_wu2_h);  cudaGetSymbolAddress((void**)&wu2_l,  g_wu2_l);
    cudaGetSymbolAddress((void**)&wout_h, g_wout_h); cudaGetSymbolAddress((void**)&wout_l, g_wout_l);
    cudaGetSymbolAddress((void**)&wu1b_h, g_wu1b_h); cudaGetSymbolAddress((void**)&wu1b_l, g_wu1b_l);
    cudaGetSymbolAddress((void**)&wm2_h,  g_wm2_h);  cudaGetSymbolAddress((void**)&wm2_l,  g_wm2_l);

    static cudaStream_t sB = nullptr;
    static cudaEvent_t evStart = nullptr, evZ = nullptr, evPrep = nullptr;
    if (sB == nullptr) {
        cudaStreamCreateWithFlags(&sB, cudaStreamNonBlocking);
        cudaEventCreateWithFlags(&evStart, cudaEventDisableTiming);
        cudaEventCreateWithFlags(&evZ,     cudaEventDisableTiming);
        cudaEventCreateWithFlags(&evPrep,  cudaEventDisableTiming);
    }
    cudaStream_t s0 = (cudaStream_t)0;

    cudaEventRecord(evStart, s0);
    cudaStreamWaitEvent(sB, evStart, 0);

    // ---- stream A: build_z -> cdist -> topk ----
    build_z_kernel<<<BN_, 192, 0, s0>>>(x_c, x_d0, x_d1, x_d2, x_o, t_emb, z, zh, zl);
    cudaEventRecord(evZ, s0);
    cdist_kernel<<<528, 512, 0, s0>>>(z + 256, dist);
    topk_kernel<<<BN_/8, 256, 0, s0>>>(dist, idx, ew);

    // ---- stream B: weight prep + s-GEMM + layer-0 Pp/Qq ----
    rearrange_w_kernel<<<(NL*1088*HH)/256, 256, 0, sB>>>(Wm1, Wu1, wp, wq, wcat);
    bias_u1_kernel<<<NL, 256, 0, sB>>>(bm2, bu1, Wu1, b2u);
    bout_kernel<<<1, DD, 0, sB>>>(b_out, bout);
    wsplit_all_kernel<<<(SP6 + 255)/256, 256, 0, sB>>>(W_in, wp, wq, Wu2, W_out, Wu1, Wm2,
                                                       win_h, win_l, wp_h, wp_l, wq_h, wq_l,
                                                       wu2_h, wu2_l, wout_h, wout_l,
                                                       wu1b_h, wu1b_l, wm2_h, wm2_l);
    wmu_gemm<<<dim3(4,4,NL), 128, 0, sB>>>(wm2_h, wm2_l, wu1b_h, wu1b_l, wcat);
    wsplit_kernel<<<(NL*2*HH*HH + 255)/256, 256, 0, sB>>>(wcat, wcat_h, wcat_l, NL*2*HH*HH);

    dim3 gB(HH/64, BN_/64);
    dim3 gPQ(HH/64, BN_/64, 2);
    dim3 gO(DD/64, BN_/64);

    cudaStreamWaitEvent(sB, evZ, 0);
    // s = x @ W_in + b_in  -> Z[:, 0:256] fp32 + planes
    gemm64<0,0><<<gB, 128, 0, sB>>>(zh + 256, zl + 256, ZW, win_h, win_l, HH,
                                    b_in, z, zh, zl, ZW, DD);
    // layer-0 Pp/Qq (independent of topk)
    pq_gemm<<<gPQ, 128, 0, sB>>>(zh, zl, wp_h, wp_l, wq_h, wq_l, bm1, pp, qq);
    cudaEventRecord(evPrep, sB);

    // ---- join: stream A continues the serial tail ----
    cudaStreamWaitEvent(s0, evPrep, 0);

    for (int l = 0; l < NL; l++) {
        const u16* wch = wcat_h + (size_t)l * 2*HH * HH;
        const u16* wcl = wcat_l + (size_t)l * 2*HH * HH;
        const u16* w2h = wu2_h + (size_t)l * HH * HH;
        const u16* w2l = wu2_l + (size_t)l * HH * HH;

        if (l > 0) {
            const u16* wph = wp_h + (size_t)l * 384 * HH;
            const u16* wpl = wp_l + (size_t)l * 384 * HH;
            const u16* wqh = wq_h + (size_t)l * 448 * HH;
            const u16* wql = wq_l + (size_t)l * 448 * HH;
            pq_gemm<<<gPQ, 128, 0, s0>>>(zh, zl, wph, wpl, wqh, wql, bm1 + l*HH, pp, qq);
        }
        // cat planes = [s | sum_k ew*gelu(Pp[src]+Qq[i])]
        edge_agg_kernel<<<BN_, 256, 0, s0>>>(pp, qq, zh, zl, idx, ew, cath, catl);
        // u1 = gelu(cat @ [Wu1a; Wm2@Wu1b] + b2u) -> planes only
        gemm64<1,0><<<gB, 128, 0, s0>>>(cath, catl, 2*HH, wch, wcl, HH,
                                        b2u + l*HH, nullptr, u1h, u1l, HH, 2*HH);
        // s += u1 @ Wu2 + bu2  (fp32 z + planes)
        gemm64<0,1><<<gB, 128, 0, s0>>>(u1h, u1l, HH, w2h, w2l, HH,
                                        bu2 + l*HH, z, zh, zl, ZW, HH);
    }

    // out = s @ W_out' + b_out'  (centering folded into weights) -> d_out directly
    gemm64<0,0><<<gO, 128, 0, s0>>>(zh, zl, ZW, wout_h, wout_l, DD,
                                    bout, out, nullptr, nullptr, DD, HH);
}

// round 16
// speedup vs baseline: 1.0398x; 1.0120x over previous
#include <cuda_runtime.h>
#include <cuda_bf16.h>
#include <math.h>

#define BN_ 4096      // batch
#define DD  128       // feature dim
#define HH  256       // hidden
#define TT  64        // time emb
#define KNN 10
#define NL  2
#define ZW  448       // Z row width: [s(256) | x(128) | t(64)]

typedef unsigned long long u64;
typedef unsigned int u32;
typedef unsigned short u16;

// ---------------- static scratch ----------------
__device__ __align__(128) float g_z[BN_*ZW];             // [s | x | t] fp32
__device__ __align__(128) u16   g_zh[BN_*ZW], g_zl[BN_*ZW];      // bf16 planes of Z
__device__ __align__(128) float g_dist[(size_t)BN_*BN_]; // 64 MB
__device__ __align__(128) float g_tmin[BN_*32];          // per-row per-tile minima
__device__ __align__(128) int   g_idx[BN_*KNN];
__device__ __align__(128) float g_ew[BN_*KNN];
__device__ __align__(128) float g_pp[BN_*HH];
__device__ __align__(128) float g_qq[BN_*HH];
__device__ __align__(128) u16   g_cath[BN_*2*HH], g_catl[BN_*2*HH];
__device__ __align__(128) u16   g_u1h[BN_*HH],    g_u1l[BN_*HH];
__device__ __align__(128) float g_wp[NL*384*HH];         // [W1a; W1c] fp32 staging
__device__ __align__(128) float g_wq[NL*448*HH];         // [W1b; -W1c; W1d] fp32 staging
__device__ __align__(128) float g_wcat[NL*2*HH*HH];      // [Wu1a; Wm2@Wu1b] fp32 staging
__device__ __align__(128) float g_b2u[NL*HH];            // bm2@Wu1b + bu1
__device__ __align__(128) float g_bout[DD];              // centered b_out
// pre-split bf16 weight planes
__device__ __align__(128) u16 g_win_h[DD*HH],        g_win_l[DD*HH];
__device__ __align__(128) u16 g_wp_h[NL*384*HH],     g_wp_l[NL*384*HH];
__device__ __align__(128) u16 g_wq_h[NL*448*HH],     g_wq_l[NL*448*HH];
__device__ __align__(128) u16 g_wcat_h[NL*2*HH*HH],  g_wcat_l[NL*2*HH*HH];
__device__ __align__(128) u16 g_wu2_h[NL*HH*HH],     g_wu2_l[NL*HH*HH];
__device__ __align__(128) u16 g_wout_h[HH*DD],       g_wout_l[HH*DD];
__device__ __align__(128) u16 g_wu1b_h[NL*HH*HH],    g_wu1b_l[NL*HH*HH];
__device__ __align__(128) u16 g_wm2_h[NL*HH*HH],     g_wm2_l[NL*HH*HH];

__device__ __forceinline__ float gelu_exact(float x) {
    return 0.5f * x * (1.0f + erff(x * 0.70710678118654752440f));
}

__device__ __forceinline__ u64 pack_f2(float x, float y) {
    u64 r; asm("mov.b64 %0, {%1, %2};" : "=l"(r) : "f"(x), "f"(y)); return r;
}
__device__ __forceinline__ float2 unpack_f2(u64 v) {
    float2 f; asm("mov.b64 {%0, %1}, %2;" : "=f"(f.x), "=f"(f.y) : "l"(v)); return f;
}
__device__ __forceinline__ void l1_acc(u64& acc, u64 a, u64 nb) {
    u64 d;
    asm("add.rn.f32x2 %0, %1, %2;" : "=l"(d) : "l"(a), "l"(nb));
    u32 lo = (u32)d & 0x7fffffffu;
    u32 hi = (u32)(d >> 32) & 0x7fffffffu;
    u64 m = ((u64)hi << 32) | (u64)lo;
    asm("add.rn.f32x2 %0, %0, %1;" : "+l"(acc) : "l"(m));
}

// ---------------- bf16 helpers ----------------
__device__ __forceinline__ void split_pair(float x0, float x1, u32& hi, u32& lo) {
    asm("cvt.rn.bf16x2.f32 %0, %1, %2;" : "=r"(hi) : "f"(x1), "f"(x0));
    float h0 = __uint_as_float(hi << 16);
    float h1 = __uint_as_float(hi & 0xffff0000u);
    float l0 = x0 - h0, l1 = x1 - h1;
    asm("cvt.rn.bf16x2.f32 %0, %1, %2;" : "=r"(lo) : "f"(l1), "f"(l0));
}
__device__ __forceinline__ void mma16(float* c, const u32* a, const u32* b) {
    asm volatile("mma.sync.aligned.m16n8k16.row.col.f32.bf16.bf16.f32 "
                 "{%0,%1,%2,%3}, {%4,%5,%6,%7}, {%8,%9}, {%0,%1,%2,%3};"
                 : "+f"(c[0]), "+f"(c[1]), "+f"(c[2]), "+f"(c[3])
                 : "r"(a[0]), "r"(a[1]), "r"(a[2]), "r"(a[3]),
                   "r"(b[0]), "r"(b[1]));
}
__device__ __forceinline__ void ldsm2t(u32& r0, u32& r1, u32 addr) {
    asm volatile("ldmatrix.sync.aligned.m8n8.x2.trans.shared.b16 {%0,%1}, [%2];"
                 : "=r"(r0), "=r"(r1) : "r"(addr));
}
__device__ __forceinline__ void ldsm4(u32* r, u32 addr) {
    asm volatile("ldmatrix.sync.aligned.m8n8.x4.shared.b16 {%0,%1,%2,%3}, [%4];"
                 : "=r"(r[0]), "=r"(r[1]), "=r"(r[2]), "=r"(r[3]) : "r"(addr));
}
__device__ __forceinline__ u32 smem_u32(const void* p) {
    return (u32)__cvta_generic_to_shared(p);
}
__device__ __forceinline__ void cp16(u32 dst, const void* src) {
    asm volatile("cp.async.cg.shared.global [%0], [%1], 16;\n" :: "r"(dst), "l"(src));
}
__device__ __forceinline__ void split1(float x, u16* hi, u16* lo, size_t i) {
    __nv_bfloat16 h = __float2bfloat16_rn(x);
    float hf = __bfloat162float(h);
    __nv_bfloat16 l = __float2bfloat16_rn(x - hf);
    hi[i] = *(u16*)&h;
    lo[i] = *(u16*)&l;
}

// ---------------- build Z = [s(later) | x | t] + planes ----------------
__global__ void build_z_kernel(const float* __restrict__ xc, const float* __restrict__ d0,
                               const float* __restrict__ d1, const float* __restrict__ d2,
                               const float* __restrict__ xo, const float* __restrict__ te,
                               float* __restrict__ Z, u16* __restrict__ Zh, u16* __restrict__ Zl) {
    int i = blockIdx.x;
    int t = threadIdx.x; // 192
    float v; int c;
    if (t < 128) {
        if (t < 64)       v = xc[i*64 + t];
        else if (t < 80)  v = d0[i*16 + (t-64)];
        else if (t < 96)  v = d1[i*16 + (t-80)];
        else if (t < 112) v = d2[i*16 + (t-96)];
        else              v = xo[i*16 + (t-112)];
        c = 256 + t;
    } else {
        v = te[i*TT + (t-128)];
        c = 384 + (t-128);
    }
    size_t o = (size_t)i*ZW + c;
    Z[o] = v;
    split1(v, Zh, Zl, o);
}

// ---------------- rearranged weights (fp32 staging) ----------------
__global__ void rearrange_w_kernel(const float* __restrict__ Wm1,
                                   const float* __restrict__ Wu1,
                                   float* __restrict__ Wp, float* __restrict__ Wq,
                                   float* __restrict__ Wcat) {
    int idx = blockIdx.x * 256 + threadIdx.x;
    int l = idx / (1088*HH);
    int r2 = idx - l*(1088*HH);
    int r = r2 / HH, c = r2 - (r2/HH)*HH;
    const float* w = Wm1 + (size_t)l*704*HH;
    if (r < 384) {
        int sr = (r < 256) ? r : (512 + (r - 256));
        Wp[(size_t)l*384*HH + r*HH + c] = w[sr*HH + c];
    } else if (r < 832) {
        int rq = r - 384;
        float sgn = 1.0f; int sr;
        if (rq < 256)      sr = 256 + rq;
        else if (rq < 384) { sr = 512 + (rq - 256); sgn = -1.0f; }
        else               sr = 640 + (rq - 384);
        Wq[(size_t)l*448*HH + rq*HH + c] = sgn * w[sr*HH + c];
    } else {
        int rc = r - 832;
        Wcat[(size_t)l*2*HH*HH + rc*HH + c] = Wu1[(size_t)l*2*HH*HH + rc*HH + c];
    }
}

// ---------------- fold bias: b2u = bm2 @ Wu1b + bu1 ----------------
__global__ void bias_u1_kernel(const float* __restrict__ bm2, const float* __restrict__ bu1,
                               const float* __restrict__ Wu1, float* __restrict__ b2u) {
    int l = blockIdx.x;
    int c = threadIdx.x;
    const float* wb = Wu1 + (size_t)l*2*HH*HH + (size_t)HH*HH;
    float acc = bu1[l*HH + c];
    for (int k = 0; k < HH; k++) acc = fmaf(bm2[l*HH + k], wb[k*HH + c], acc);
    b2u[l*HH + c] = acc;
}

// ---------------- centered b_out ----------------
__global__ void bout_kernel(const float* __restrict__ b_out, float* __restrict__ bout_c) {
    int c = threadIdx.x; // 128
    float v = b_out[c];
    if (c >= 64 && c < 112) {
        int blk = 64 + (((c - 64) >> 4) << 4);
        float m = 0.0f;
        #pragma unroll
        for (int q = 0; q < 16; q++) m += b_out[blk + q];
        v -= m * (1.0f/16.0f);
    }
    bout_c[c] = v;
}

// one launch for all independent weight splits (W_out centered on the fly)
#define SP0 (DD*HH)
#define SP1 (SP0 + NL*384*HH)
#define SP2 (SP1 + NL*448*HH)
#define SP3 (SP2 + NL*HH*HH)
#define SP4 (SP3 + HH*DD)
#define SP5 (SP4 + NL*HH*HH)
#define SP6 (SP5 + NL*HH*HH)
__global__ void wsplit_all_kernel(const float* __restrict__ W_in,
                                  const float* __restrict__ wp,
                                  const float* __restrict__ wq,
                                  const float* __restrict__ Wu2,
                                  const float* __restrict__ W_out,
                                  const float* __restrict__ Wu1,
                                  const float* __restrict__ Wm2,
                                  u16* win_h, u16* win_l, u16* wp_h, u16* wp_l,
                                  u16* wq_h, u16* wq_l, u16* wu2_h, u16* wu2_l,
                                  u16* wout_h, u16* wout_l, u16* wu1b_h, u16* wu1b_l,
                                  u16* wm2_h, u16* wm2_l) {
    int i = blockIdx.x * 256 + threadIdx.x;
    if (i < SP0) {
        split1(W_in[i], win_h, win_l, i);
    } else if (i < SP1) {
        int j = i - SP0; split1(wp[j], wp_h, wp_l, j);
    } else if (i < SP2) {
        int j = i - SP1; split1(wq[j], wq_h, wq_l, j);
    } else if (i < SP3) {
        int j = i - SP2; split1(Wu2[j], wu2_h, wu2_l, j);
    } else if (i < SP4) {
        int j = i - SP3;                 // r*DD + c
        int c = j & (DD-1);
        float v = W_out[j];
        if (c >= 64 && c < 112) {        // center categorical blocks (exact linear fold)
            int blk = j - c + 64 + (((c - 64) >> 4) << 4);
            float m = 0.0f;
            #pragma unroll
            for (int q = 0; q < 16; q++) m += W_out[blk + q];
            v -= m * (1.0f/16.0f);
        }
        split1(v, wout_h, wout_l, j);
    } else if (i < SP5) {
        int j = i - SP4;
        int l = j >> 16;
        int e = j & 65535;
        split1(Wu1[(size_t)l*2*HH*HH + (size_t)HH*HH + e], wu1b_h, wu1b_l, j);
    } else if (i < SP6) {
        int j = i - SP5; split1(Wm2[j], wm2_h, wm2_l, j);
    }
}

__global__ void wsplit_kernel(const float* __restrict__ src, u16* __restrict__ hi,
                              u16* __restrict__ lo, int n) {
    int i = blockIdx.x * 256 + threadIdx.x;
    if (i >= n) return;
    split1(src[i], hi, lo, i);
}

// ---------------- symmetric L1 cdist + per-tile row minima ----------------
__global__ __launch_bounds__(512) void cdist_kernel(const float* __restrict__ X,
                                                    float* __restrict__ Dist,
                                                    float* __restrict__ Tmin) {
    __shared__ u64 As2[16][128];
    __shared__ u64 Bs2[4][17][33];   // [j][kk][col], conflict-free consumer reads
    __shared__ float scm[128][17];   // transposed col-min staging [col][ty]
    int r = 0, rem = blockIdx.x;
    while (rem >= 32 - r) { rem -= 32 - r; r++; }
    int bm = r * 128, bn = (r + rem) * 128;

    int tid = threadIdx.x;
    int ty = tid >> 5;
    int tx = tid & 31;
    u64 acc2[8][4];
    #pragma unroll
    for (int i = 0; i < 8; i++)
        #pragma unroll
        for (int j = 0; j < 4; j++) acc2[i][j] = 0ull;

    int lrow = tid >> 2;
    int lq   = (tid & 3) * 8;
    int jb = lrow & 3, cb = lrow >> 2;
    int ks = lq >> 1;

    for (int k0 = 0; k0 < DD; k0 += 32) {
        float4 va0 = *(const float4*)&X[(size_t)(bm + lrow)*ZW + k0 + lq];
        float4 va1 = *(const float4*)&X[(size_t)(bm + lrow)*ZW + k0 + lq + 4];
        As2[ks+0][lrow] = pack_f2(va0.x, va0.y);
        As2[ks+1][lrow] = pack_f2(va0.z, va0.w);
        As2[ks+2][lrow] = pack_f2(va1.x, va1.y);
        As2[ks+3][lrow] = pack_f2(va1.z, va1.w);
        float4 vb0 = *(const float4*)&X[(size_t)(bn + lrow)*ZW + k0 + lq];
        float4 vb1 = *(const float4*)&X[(size_t)(bn + lrow)*ZW + k0 + lq + 4];
        Bs2[jb][ks+0][cb] = pack_f2(-vb0.x, -vb0.y);
        Bs2[jb][ks+1][cb] = pack_f2(-vb0.z, -vb0.w);
        Bs2[jb][ks+2][cb] = pack_f2(-vb1.x, -vb1.y);
        Bs2[jb][ks+3][cb] = pack_f2(-vb1.z, -vb1.w);
        __syncthreads();
        #pragma unroll
        for (int kk = 0; kk < 16; kk++) {
            u64 a2[8], b2[4];
            #pragma unroll
            for (int i = 0; i < 8; i++) a2[i] = As2[kk][ty*8 + i];
            #pragma unroll
            for (int j = 0; j < 4; j++) b2[j] = Bs2[j][kk][tx];
            #pragma unroll
            for (int i = 0; i < 8; i++)
                #pragma unroll
                for (int j = 0; j < 4; j++) l1_acc(acc2[i][j], a2[i], b2[j]);
        }
        __syncthreads();
    }
    float res[8][4];
    #pragma unroll
    for (int i = 0; i < 8; i++)
        #pragma unroll
        for (int j = 0; j < 4; j++) {
            float2 f = unpack_f2(acc2[i][j]);
            res[i][j] = f.x + f.y;
        }
    if (bm == bn) {
        #pragma unroll
        for (int i = 0; i < 8; i++)
            #pragma unroll
            for (int j = 0; j < 4; j++)
                if (ty*8 + i == tx*4 + j) res[i][j] = __int_as_float(0x7f800000);
    }
    // normal stores
    #pragma unroll
    for (int i = 0; i < 8; i++) {
        float4 v = make_float4(res[i][0], res[i][1], res[i][2], res[i][3]);
        *(float4*)&Dist[(size_t)(bm + ty*8 + i)*BN_ + bn + tx*4] = v;
    }
    // per-row tile minima (normal orientation): warp shfl over tx
    #pragma unroll
    for (int i = 0; i < 8; i++) {
        float m = fminf(fminf(res[i][0], res[i][1]), fminf(res[i][2], res[i][3]));
        #pragma unroll
        for (int off = 16; off >= 1; off >>= 1)
            m = fminf(m, __shfl_xor_sync(0xffffffffu, m, off));
        if (tx == 0) Tmin[(size_t)(bm + ty*8 + i)*32 + (bn >> 7)] = m;
    }
    if (bm != bn) {
        // transposed stores
        #pragma unroll
        for (int j = 0; j < 4; j++) {
            float4 v0 = make_float4(res[0][j], res[1][j], res[2][j], res[3][j]);
            float4 v1 = make_float4(res[4][j], res[5][j], res[6][j], res[7][j]);
            size_t o = (size_t)(bn + tx*4 + j)*BN_ + bm + ty*8;
            *(float4*)&Dist[o]     = v0;
            *(float4*)&Dist[o + 4] = v1;
        }
        // per-row tile minima (transposed orientation): smem reduce over ty
        #pragma unroll
        for (int j = 0; j < 4; j++) {
            float m = res[0][j];
            #pragma unroll
            for (int i = 1; i < 8; i++) m = fminf(m, res[i][j]);
            scm[tx*4 + j][ty] = m;
        }
        __syncthreads();
        if (tid < 128) {
            float m = scm[tid][0];
            #pragma unroll
            for (int t = 1; t < 16; t++) m = fminf(m, scm[tid][t]);
            Tmin[(size_t)(bn + tid)*32 + (bm >> 7)] = m;
        }
    }
}

// ---------------- top-K: single filtered pass using precomputed tile minima ----------------
__global__ __launch_bounds__(256) void topk_kernel(const float* __restrict__ Dist,
                                                   const float* __restrict__ Tmin,
                                                   int* __restrict__ Idx,
                                                   float* __restrict__ Ew) {
    __shared__ float sdm[8][32*KNN];
    __shared__ int   sim[8][32*KNN];
    int warp = threadIdx.x >> 5;
    int lane = threadIdx.x & 31;
    int i = blockIdx.x * 8 + warp;
    const float4* row = (const float4*)(Dist + (size_t)i * BN_);
    const float INF = __int_as_float(0x7f800000);

    // T = 10th smallest of the 32 per-tile row minima (valid upper bound on d10)
    float cur = Tmin[(size_t)i*32 + lane];
    float T = INF;
    #pragma unroll
    for (int q = 0; q < KNN; q++) {
        float wmin = cur;
        #pragma unroll
        for (int off = 16; off >= 1; off >>= 1)
            wmin = fminf(wmin, __shfl_xor_sync(0xffffffffu, wmin, off));
        T = wmin;
        u32 ballot = __ballot_sync(0xffffffffu, cur == wmin);
        int first = __ffs(ballot) - 1;
        if (lane == first) cur = INF;
    }

    float bd[KNN]; int bi[KNN];
    #pragma unroll
    for (int q = 0; q < KNN; q++) { bd[q] = INF; bi[q] = 0x7fffffff; }
    #pragma unroll 4
    for (int it = 0; it < 32; it++) {
        int jv = it*32 + lane;
        float4 d4 = row[jv];
        float dv[4] = {d4.x, d4.y, d4.z, d4.w};
        #pragma unroll
        for (int q4 = 0; q4 < 4; q4++) {
            float d = dv[q4];
            if (d <= T) {
                float dd = d; int ii = jv*4 + q4;
                #pragma unroll
                for (int q = 0; q < KNN; q++) {
                    bool c = dd < bd[q];
                    float tf = bd[q]; int ti = bi[q];
                    bd[q] = c ? dd : bd[q]; bi[q] = c ? ii : bi[q];
                    dd = c ? tf : dd;       ii = c ? ti : ii;
                }
            }
        }
    }

    float* sdw = sdm[warp];
    int*   siw = sim[warp];
    #pragma unroll
    for (int q = 0; q < KNN; q++) { sdw[lane*KNN + q] = bd[q]; siw[lane*KNN + q] = bi[q]; }
    __syncwarp();
    #pragma unroll
    for (int stride = 1; stride < 32; stride <<= 1) {
        if ((lane & (2*stride - 1)) == 0) {
            float* da = sdw + lane*KNN;            int* ia = siw + lane*KNN;
            float* db = sdw + (lane+stride)*KNN;   int* ib = siw + (lane+stride)*KNN;
            float od[KNN]; int oi[KNN];
            int pa = 0, pb = 0;
            #pragma unroll
            for (int q = 0; q < KNN; q++) {
                float va = da[pa], vb = db[pb];
                bool c = va <= vb;
                od[q] = c ? va : vb;
                oi[q] = c ? ia[pa] : ib[pb];
                pa += c; pb += !c;
            }
            #pragma unroll
            for (int q = 0; q < KNN; q++) { da[q] = od[q]; ia[q] = oi[q]; }
        }
        __syncwarp();
    }

    if (lane == 0) {
        float d[KNN]; int ix[KNN];
        #pragma unroll
        for (int q = 0; q < KNN; q++) { d[q] = sdw[q]; ix[q] = siw[q]; }
        float w[KNN], sum = 0.0f;
        float dmin = d[0];
        #pragma unroll
        for (int q = 0; q < KNN; q++) { w[q] = expf(dmin - d[q]); sum += w[q]; }
        float inv = 1.0f / sum;
        #pragma unroll
        for (int q = 0; q < KNN; q++) {
            Ew[i*KNN + q] = w[q] * inv;
            Idx[i*KNN + q] = ix[q];
        }
    }
}

// ---- bf16 tensor-core GEMM: pre-split A AND B planes, pure-ldmatrix mainloop ----
template<int ACT, int ACC>
__device__ __forceinline__ void gemm_bf(const u16* __restrict__ Ahi_g,
                                        const u16* __restrict__ Alo_g, int lda,
                                        const u16* __restrict__ Whi,
                                        const u16* __restrict__ Wlo, int ldw,
                                        const float* __restrict__ bias,
                                        float* __restrict__ C,
                                        u16* __restrict__ Chi, u16* __restrict__ Clo,
                                        int ldc, int K, int bm, int bn) {
    __shared__ alignas(16) u16 Ah[2][64][40];
    __shared__ alignas(16) u16 Al[2][64][40];
    __shared__ alignas(16) u16 Bh[2][32][72];
    __shared__ alignas(16) u16 Bl[2][32][72];
    int tid = threadIdx.x, lane = tid & 31, wid = tid >> 5;
    int wm = (wid >> 1) * 32, wn = (wid & 1) * 32;
    float c[2][4][4];
    #pragma unroll
    for (int mb = 0; mb < 2; mb++)
        #pragma unroll
        for (int nb = 0; nb < 4; nb++)
            #pragma unroll
            for (int q = 0; q < 4; q++) c[mb][nb][q] = 0.0f;

    int as0 = tid, as1 = tid + 128;
    int ar0 = as0 >> 2, ao0 = (as0 & 3) * 8;
    int ar1 = as1 >> 2, ao1 = (as1 & 3) * 8;
    int brow = tid >> 2, bcol = (tid & 3) * 16;

    const u16* ah0 = &Ahi_g[(size_t)(bm + ar0)*lda + ao0];
    const u16* ah1 = &Ahi_g[(size_t)(bm + ar1)*lda + ao1];
    const u16* al0 = &Alo_g[(size_t)(bm + ar0)*lda + ao0];
    const u16* al1 = &Alo_g[(size_t)(bm + ar1)*lda + ao1];
    const u16* bh0 = &Whi[(size_t)brow*ldw + bn + bcol];
    const u16* bl0 = &Wlo[(size_t)brow*ldw + bn + bcol];

    {
        cp16(smem_u32(&Ah[0][ar0][ao0]), ah0);
        cp16(smem_u32(&Ah[0][ar1][ao1]), ah1);
        cp16(smem_u32(&Al[0][ar0][ao0]), al0);
        cp16(smem_u32(&Al[0][ar1][ao1]), al1);
        u32 dh = smem_u32(&Bh[0][brow][bcol]);
        cp16(dh, bh0); cp16(dh+16, bh0+8);
        u32 dl = smem_u32(&Bl[0][brow][bcol]);
        cp16(dl, bl0); cp16(dl+16, bl0+8);
        asm volatile("cp.async.commit_group;\n");
    }

    int nch = K >> 5;
    for (int ch = 0; ch < nch; ch++) {
        int buf = ch & 1;
        if (ch + 1 < nch) {
            int k0 = (ch + 1) * 32;
            cp16(smem_u32(&Ah[buf^1][ar0][ao0]), ah0 + k0);
            cp16(smem_u32(&Ah[buf^1][ar1][ao1]), ah1 + k0);
            cp16(smem_u32(&Al[buf^1][ar0][ao0]), al0 + k0);
            cp16(smem_u32(&Al[buf^1][ar1][ao1]), al1 + k0);
            u32 dh = smem_u32(&Bh[buf^1][brow][bcol]);
            const u16* sh = bh0 + (size_t)k0*ldw;
            cp16(dh, sh); cp16(dh+16, sh+8);
            u32 dl = smem_u32(&Bl[buf^1][brow][bcol]);
            const u16* sl = bl0 + (size_t)k0*ldw;
            cp16(dl, sl); cp16(dl+16, sl+8);
            asm volatile("cp.async.commit_group;\n");
            asm volatile("cp.async.wait_group 1;\n");
        } else {
            asm volatile("cp.async.wait_group 0;\n");
        }
        __syncthreads();
        #pragma unroll
        for (int ks = 0; ks < 32; ks += 16) {
            u32 ahi[2][4], alo[2][4];
            int arow = (lane & 7) + ((lane >> 3) & 1) * 8;
            int acol = ks + (lane >> 4) * 8;
            #pragma unroll
            for (int mb = 0; mb < 2; mb++) {
                ldsm4(ahi[mb], smem_u32(&Ah[buf][wm + mb*16 + arow][acol]));
                ldsm4(alo[mb], smem_u32(&Al[buf][wm + mb*16 + arow][acol]));
            }
            u32 bhi[4][2], blo[4][2];
            int krow = ks + (lane & 7) + ((lane >> 3) & 1) * 8;
            #pragma unroll
            for (int nb = 0; nb < 4; nb++) {
                int n0 = wn + nb*8;
                ldsm2t(bhi[nb][0], bhi[nb][1], smem_u32(&Bh[buf][krow][n0]));
                ldsm2t(blo[nb][0], blo[nb][1], smem_u32(&Bl[buf][krow][n0]));
            }
            #pragma unroll
            for (int mb = 0; mb < 2; mb++)
                #pragma unroll
                for (int nb = 0; nb < 4; nb++) {
                    mma16(c[mb][nb], ahi[mb], bhi[nb]);
                    mma16(c[mb][nb], alo[mb], bhi[nb]);
                    mma16(c[mb][nb], ahi[mb], blo[nb]);
                }
        }
        __syncthreads();
    }

    int er = lane >> 2, ec = (lane & 3) * 2;
    #pragma unroll
    for (int mb = 0; mb < 2; mb++) {
        #pragma unroll
        for (int nb = 0; nb < 4; nb++) {
            int col = bn + wn + nb*8 + ec;
            float bv0 = bias ? bias[col]   : 0.0f;
            float bv1 = bias ? bias[col+1] : 0.0f;
            #pragma unroll
            for (int half = 0; half < 2; half++) {
                int rrow = bm + wm + mb*16 + er + half*8;
                size_t o = (size_t)rrow*ldc + col;
                float v0 = c[mb][nb][half*2+0] + bv0;
                float v1 = c[mb][nb][half*2+1] + bv1;
                if (ACC) { v0 += C[o]; v1 += C[o+1]; }
                if (ACT) { v0 = gelu_exact(v0); v1 = gelu_exact(v1); }
                if (C) { C[o] = v0; C[o+1] = v1; }
                if (Chi) {
                    u32 h, l;
                    split_pair(v0, v1, h, l);
                    *(u32*)(Chi + o) = h;
                    *(u32*)(Clo + o) = l;
                }
            }
        }
    }
}

template<int ACT, int ACC>
__global__ __launch_bounds__(128) void gemm64(const u16* __restrict__ Ahi,
                                              const u16* __restrict__ Alo, int lda,
                                              const u16* __restrict__ Whi,
                                              const u16* __restrict__ Wlo, int ldw,
                                              const float* __restrict__ bias,
                                              float* __restrict__ C,
                                              u16* __restrict__ Chi, u16* __restrict__ Clo,
                                              int ldc, int K) {
    gemm_bf<ACT,ACC>(Ahi, Alo, lda, Whi, Wlo, ldw, bias, C, Chi, Clo, ldc, K,
                     blockIdx.y*64, blockIdx.x*64);
}

// z-batched Pp/Qq GEMMs (A = Z planes)
__global__ __launch_bounds__(128) void pq_gemm(const u16* __restrict__ Zh, const u16* __restrict__ Zl,
                                               const u16* __restrict__ WpH, const u16* __restrict__ WpL,
                                               const u16* __restrict__ WqH, const u16* __restrict__ WqL,
                                               const float* __restrict__ bm1l,
                                               float* __restrict__ Pp,
                                               float* __restrict__ Qq) {
    if (blockIdx.z == 0)
        gemm_bf<0,0>(Zh, Zl, ZW, WpH, WpL, HH, nullptr, Pp, nullptr, nullptr, HH, 384,
                     blockIdx.y*64, blockIdx.x*64);
    else
        gemm_bf<0,0>(Zh, Zl, ZW, WqH, WqL, HH, bm1l, Qq, nullptr, nullptr, HH, 448,
                     blockIdx.y*64, blockIdx.x*64);
}

// Wmu = Wm2 @ Wu1b for both layers (z = layer)
__global__ __launch_bounds__(128) void wmu_gemm(const u16* __restrict__ Wm2H,
                                                const u16* __restrict__ Wm2L,
                                                const u16* __restrict__ Wu1bH,
                                                const u16* __restrict__ Wu1bL,
                                                float* __restrict__ Wcat) {
    int l = blockIdx.z;
    gemm_bf<0,0>(Wm2H + (size_t)l*HH*HH, Wm2L + (size_t)l*HH*HH, HH,
                 Wu1bH + (size_t)l*HH*HH, Wu1bL + (size_t)l*HH*HH, HH,
                 nullptr, Wcat + (size_t)l*2*HH*HH + (size_t)HH*HH, nullptr, nullptr,
                 HH, HH, blockIdx.y*64, blockIdx.x*64);
}

// ---------------- fused edge kernel: cat planes = [s | sum_k ew*gelu(Pp[src]+Qq)] ----------------
__global__ __launch_bounds__(256) void edge_agg_kernel(const float* __restrict__ Pp,
                                                       const float* __restrict__ Qq,
                                                       const u16* __restrict__ Zh,
                                                       const u16* __restrict__ Zl,
                                                       const int* __restrict__ Idx,
                                                       const float* __restrict__ Ew,
                                                       u16* __restrict__ CatH,
                                                       u16* __restrict__ CatL) {
    int i = blockIdx.x;
    int t = threadIdx.x;
    __shared__ int   ssrc[KNN];
    __shared__ float sw[KNN];
    if (t < KNN) { ssrc[t] = Idx[i*KNN + t]; sw[t] = Ew[i*KNN + t]; }
    __syncthreads();
    float q = Qq[i*HH + t];
    float acc = 0.0f;
    #pragma unroll
    for (int k = 0; k < KNN; k++) {
        float p = Pp[(size_t)ssrc[k]*HH + t];
        acc = fmaf(sw[k], gelu_exact(p + q), acc);
    }
    size_t ob = (size_t)i*2*HH;
    split1(acc, CatH, CatL, ob + HH + t);
    CatH[ob + t] = Zh[(size_t)i*ZW + t];
    CatL[ob + t] = Zl[(size_t)i*ZW + t];
}

// ---------------- launcher ----------------
extern "C" void kernel_launch(void* const* d_in, const int* in_sizes, int n_in,
                              void* d_out, int out_size) {
    const float* x_c   = (const float*)d_in[0];
    const float* x_d0  = (const float*)d_in[1];
    const float* x_d1  = (const float*)d_in[2];
    const float* x_d2  = (const float*)d_in[3];
    const float* x_o   = (const float*)d_in[4];
    const float* t_emb = (const float*)d_in[5];
    const float* W_in  = (const float*)d_in[6];
    const float* b_in  = (const float*)d_in[7];
    const float* Wm1   = (const float*)d_in[8];
    const float* bm1   = (const float*)d_in[9];
    const float* Wm2   = (const float*)d_in[10];
    const float* bm2   = (const float*)d_in[11];
    const float* Wu1   = (const float*)d_in[12];
    const float* bu1   = (const float*)d_in[13];
    const float* Wu2   = (const float*)d_in[14];
    const float* bu2   = (const float*)d_in[15];
    const float* W_out = (const float*)d_in[16];
    const float* b_out = (const float*)d_in[17];
    float* out = (float*)d_out;

    float *z, *dist, *tmin, *ew, *pp, *qq, *wp, *wq, *wcat, *b2u, *bout;
    int* idx;
    u16 *zh, *zl, *cath, *catl, *u1h, *u1l;
    u16 *win_h, *win_l, *wp_h, *wp_l, *wq_h, *wq_l, *wcat_h, *wcat_l;
    u16 *wu2_h, *wu2_l, *wout_h, *wout_l, *wu1b_h, *wu1b_l, *wm2_h, *wm2_l;
    cudaGetSymbolAddress((void**)&z,    g_z);
    cudaGetSymbolAddress((void**)&zh,   g_zh);
    cudaGetSymbolAddress((void**)&zl,   g_zl);
    cudaGetSymbolAddress((void**)&dist, g_dist);
    cudaGetSymbolAddress((void**)&tmin, g_tmin);
    cudaGetSymbolAddress((void**)&idx,  g_idx);
    cudaGetSymbolAddress((void**)&ew,   g_ew);
    cudaGetSymbolAddress((void**)&pp,   g_pp);
    cudaGetSymbolAddress((void**)&qq,   g_qq);
    cudaGetSymbolAddress((void**)&cath, g_cath);
    cudaGetSymbolAddress((void**)&catl, g_catl);
    cudaGetSymbolAddress((void**)&u1h,  g_u1h);
    cudaGetSymbolAddress((void**)&u1l,  g_u1l);
    cudaGetSymbolAddress((void**)&wp,   g_wp);
    cudaGetSymbolAddress((void**)&wq,   g_wq);
    cudaGetSymbolAddress((void**)&wcat, g_wcat);
    cudaGetSymbolAddress((void**)&b2u,  g_b2u);
    cudaGetSymbolAddress((void**)&bout, g_bout);
    cudaGetSymbolAddress((void**)&win_h,  g_win_h);  cudaGetSymbolAddress((void**)&win_l,  g_win_l);
    cudaGetSymbolAddress((void**)&wp_h,   g_wp_h);   cudaGetSymbolAddress((void**)&wp_l,   g_wp_l);
    cudaGetSymbolAddress((void**)&wq_h,   g_wq_h);   cudaGetSymbolAddress((void**)&wq_l,   g_wq_l);
    cudaGetSymbolAddress((void**)&wcat_h, g_wcat_h); cudaGetSymbolAddress((void**)&wcat_l, g_wcat_l);
    cudaGetSymbolAddress((void**)&wu2_h,  g_wu2_h);  cudaGetSymbolAddress((void**)&wu2_l,  g_wu2_l);
    cudaGetSymbolAddress((void**)&wout_h, g_wout_h); cudaGetSymbolAddress((void**)&wout_l, g_wout_l);
    cudaGetSymbolAddress((void**)&wu1b_h, g_wu1b_h); cudaGetSymbolAddress((void**)&wu1b_l, g_wu1b_l);
    cudaGetSymbolAddress((void**)&wm2_h,  g_wm2_h);  cudaGetSymbolAddress((void**)&wm2_l,  g_wm2_l);

    static cudaStream_t sB = nullptr;
    static cudaEvent_t evStart = nullptr, evZ = nullptr, evPrep = nullptr;
    if (sB == nullptr) {
        cudaStreamCreateWithFlags(&sB, cudaStreamNonBlocking);
        cudaEventCreateWithFlags(&evStart, cudaEventDisableTiming);
        cudaEventCreateWithFlags(&evZ,     cudaEventDisableTiming);
        cudaEventCreateWithFlags(&evPrep,  cudaEventDisableTiming);
    }
    cudaStream_t s0 = (cudaStream_t)0;

    cudaEventRecord(evStart, s0);
    cudaStreamWaitEvent(sB, evStart, 0);

    // ---- stream A: build_z -> cdist(+tile minima) -> topk ----
    build_z_kernel<<<BN_, 192, 0, s0>>>(x_c, x_d0, x_d1, x_d2, x_o, t_emb, z, zh, zl);
    cudaEventRecord(evZ, s0);
    cdist_kernel<<<528, 512, 0, s0>>>(z + 256, dist, tmin);
    topk_kernel<<<BN_/8, 256, 0, s0>>>(dist, tmin, idx, ew);

    // ---- stream B: weight prep + s-GEMM + layer-0 Pp/Qq ----
    rearrange_w_kernel<<<(NL*1088*HH)/256, 256, 0, sB>>>(Wm1, Wu1, wp, wq, wcat);
    bias_u1_kernel<<<NL, 256, 0, sB>>>(bm2, bu1, Wu1, b2u);
    bout_kernel<<<1, DD, 0, sB>>>(b_out, bout);
    wsplit_all_kernel<<<(SP6 + 255)/256, 256, 0, sB>>>(W_in, wp, wq, Wu2, W_out, Wu1, Wm2,
                                                       win_h, win_l, wp_h, wp_l, wq_h, wq_l,
                                                       wu2_h, wu2_l, wout_h, wout_l,
                                                       wu1b_h, wu1b_l, wm2_h, wm2_l);
    wmu_gemm<<<dim3(4,4,NL), 128, 0, sB>>>(wm2_h, wm2_l, wu1b_h, wu1b_l, wcat);
    wsplit_kernel<<<(NL*2*HH*HH + 255)/256, 256, 0, sB>>>(wcat, wcat_h, wcat_l, NL*2*HH*HH);

    dim3 gB(HH/64, BN_/64);
    dim3 gPQ(HH/64, BN_/64, 2);
    dim3 gO(DD/64, BN_/64);

    cudaStreamWaitEvent(sB, evZ, 0);
    // s = x @ W_in + b_in  -> Z[:, 0:256] fp32 + planes
    gemm64<0,0><<<gB, 128, 0, sB>>>(zh + 256, zl + 256, ZW, win_h, win_l, HH,
                                    b_in, z, zh, zl, ZW, DD);
    // layer-0 Pp/Qq (independent of topk)
    pq_gemm<<<gPQ, 128, 0, sB>>>(zh, zl, wp_h, wp_l, wq_h, wq_l, bm1, pp, qq);
    cudaEventRecord(evPrep, sB);

    // ---- join: stream A continues the serial tail ----
    cudaStreamWaitEvent(s0, evPrep, 0);

    for (int l = 0; l < NL; l++) {
        const u16* wch = wcat_h + (size_t)l * 2*HH * HH;
        const u16* wcl = wcat_l + (size_t)l * 2*HH * HH;
        const u16* w2h = wu2_h + (size_t)l * HH * HH;
        const u16* w2l = wu2_l + (size_t)l * HH * HH;

        if (l > 0) {
            const u16* wph = wp_h + (size_t)l * 384 * HH;
            const u16* wpl = wp_l + (size_t)l * 384 * HH;
            const u16* wqh = wq_h + (size_t)l * 448 * HH;
            const u16* wql = wq_l + (size_t)l * 448 * HH;
            pq_gemm<<<gPQ, 128, 0, s0>>>(zh, zl, wph, wpl, wqh, wql, bm1 + l*HH, pp, qq);
        }
        // cat planes = [s | sum_k ew*gelu(Pp[src]+Qq[i])]
        edge_agg_kernel<<<BN_, 256, 0, s0>>>(pp, qq, zh, zl, idx, ew, cath, catl);
        // u1 = gelu(cat @ [Wu1a; Wm2@Wu1b] + b2u) -> planes only
        gemm64<1,0><<<gB, 128, 0, s0>>>(cath, catl, 2*HH, wch, wcl, HH,
                                        b2u + l*HH, nullptr, u1h, u1l, HH, 2*HH);
        // s += u1 @ Wu2 + bu2  (fp32 z + planes)
        gemm64<0,1><<<gB, 128, 0, s0>>>(u1h, u1l, HH, w2h, w2l, HH,
                                        bu2 + l*HH, z, zh, zl, ZW, HH);
    }

    // out = s @ W_out' + b_out'  (centering folded into weights) -> d_out directly
    gemm64<0,0><<<gO, 128, 0, s0>>>(zh, zl, ZW, wout_h, wout_l, DD,
                                    bout, out, nullptr, nullptr, DD, HH);
}